// round 1
// baseline (speedup 1.0000x reference)
#include <cuda_runtime.h>
#include <math.h>

#define Bb 2
#define Ss 2048
#define Ee 1024
#define Hh 16
#define Dd 64
#define MM (Bb*Ss)          // 4096 rows
#define EPSv 1e-5f

// ---------------- scratch (static device globals; no allocation) -------------
__device__ float g_xn [MM*Ee];
__device__ float g_q  [MM*Ee];
__device__ float g_k  [MM*Ee];
__device__ float g_v  [MM*Ee];
__device__ float g_ctx[MM*Ee];
__device__ float g_h  [MM*Ee];
__device__ float g_h2 [MM*Ee];
__device__ float g_ffa[MM*4*Ee];
__device__ float g_wq2[Ee*Ee];
__device__ float g_wk2[Ee*Ee];
__device__ float g_wv2[Ee*Ee];

// ---------------- weight repack: [H,E,D] -> [E, H*D] row-major ---------------
__global__ void pack_w(const float* __restrict__ w, float* __restrict__ o) {
    int i = blockIdx.x * blockDim.x + threadIdx.x;   // over E*E
    if (i < Ee*Ee) {
        int e = i / Ee;
        int n = i % Ee;
        int h = n / Dd, d = n % Dd;
        o[i] = w[(h*Ee + e)*Dd + d];
    }
}

// ---------------- LayerNorm: one block per row of 1024 -----------------------
__global__ void ln_k(const float* __restrict__ x, const float* __restrict__ g,
                     const float* __restrict__ b, float* __restrict__ y) {
    int row = blockIdx.x;
    int t = threadIdx.x;                // 256 threads, float4 each
    float4 v = ((const float4*)(x + (size_t)row*Ee))[t];
    float s  = v.x + v.y + v.z + v.w;
    float sq = v.x*v.x + v.y*v.y + v.z*v.z + v.w*v.w;
    __shared__ float sh1[8], sh2[8];
    #pragma unroll
    for (int o = 16; o > 0; o >>= 1) {
        s  += __shfl_xor_sync(0xffffffffu, s,  o);
        sq += __shfl_xor_sync(0xffffffffu, sq, o);
    }
    int lane = t & 31, w = t >> 5;
    if (lane == 0) { sh1[w] = s; sh2[w] = sq; }
    __syncthreads();
    s = 0.f; sq = 0.f;
    #pragma unroll
    for (int i = 0; i < 8; i++) { s += sh1[i]; sq += sh2[i]; }
    float mu  = s  * (1.f/Ee);
    float var = sq * (1.f/Ee) - mu*mu;
    float rs  = rsqrtf(var + EPSv);
    float4 gv = ((const float4*)g)[t];
    float4 bv = ((const float4*)b)[t];
    float4 o4;
    o4.x = (v.x - mu)*rs*gv.x + bv.x;
    o4.y = (v.y - mu)*rs*gv.y + bv.y;
    o4.z = (v.z - mu)*rs*gv.z + bv.z;
    o4.w = (v.w - mu)*rs*gv.w + bv.w;
    ((float4*)(y + (size_t)row*Ee))[t] = o4;
}

// ---------------- SGEMM 128x128x8, 256 threads, 8x8 per thread ---------------
// EPI: 0 = +bias ; 1 = +bias +residual ; 2 = +bias then exact GELU
__device__ __forceinline__ float gelu_exact(float x) {
    return 0.5f * x * (1.0f + erff(x * 0.7071067811865476f));
}

template<int EPI>
__global__ void __launch_bounds__(256)
sgemm_k(const float* __restrict__ A, const float* __restrict__ Bm,
        const float* __restrict__ bias, const float* __restrict__ res,
        float* __restrict__ C, int M, int N, int K) {
    __shared__ float As[8][128];
    __shared__ float Bs[8][132];
    int tid  = threadIdx.x;
    int row0 = blockIdx.y * 128, col0 = blockIdx.x * 128;
    int arow = tid >> 1, acol = (tid & 1) * 4;
    int brow = tid >> 5, bcol = (tid & 31) * 4;
    int tx = tid & 15, ty = tid >> 4;

    float acc[8][8];
    #pragma unroll
    for (int i = 0; i < 8; i++)
        #pragma unroll
        for (int j = 0; j < 8; j++) acc[i][j] = 0.f;

    const float* Aptr = A + (size_t)(row0 + arow) * K + acol;
    const float* Bptr = Bm + (size_t)brow * N + col0 + bcol;

    for (int k0 = 0; k0 < K; k0 += 8) {
        float4 av = *(const float4*)(Aptr + k0);
        float4 bv = *(const float4*)(Bptr + (size_t)k0 * N);
        As[acol+0][arow] = av.x;
        As[acol+1][arow] = av.y;
        As[acol+2][arow] = av.z;
        As[acol+3][arow] = av.w;
        *(float4*)&Bs[brow][bcol] = bv;
        __syncthreads();
        #pragma unroll
        for (int kk = 0; kk < 8; kk++) {
            float a[8], b[8];
            *(float4*)(a)   = *(const float4*)&As[kk][ty*8];
            *(float4*)(a+4) = *(const float4*)&As[kk][ty*8+4];
            *(float4*)(b)   = *(const float4*)&Bs[kk][tx*8];
            *(float4*)(b+4) = *(const float4*)&Bs[kk][tx*8+4];
            #pragma unroll
            for (int i = 0; i < 8; i++)
                #pragma unroll
                for (int j = 0; j < 8; j++) acc[i][j] += a[i]*b[j];
        }
        __syncthreads();
    }

    #pragma unroll
    for (int i = 0; i < 8; i++) {
        int m = row0 + ty*8 + i;
        #pragma unroll
        for (int j = 0; j < 8; j += 4) {
            int n = col0 + tx*8 + j;
            float4 o;
            o.x = acc[i][j+0] + bias[n+0];
            o.y = acc[i][j+1] + bias[n+1];
            o.z = acc[i][j+2] + bias[n+2];
            o.w = acc[i][j+3] + bias[n+3];
            if (EPI == 1) {
                float4 rv = *(const float4*)&res[(size_t)m*N + n];
                o.x += rv.x; o.y += rv.y; o.z += rv.z; o.w += rv.w;
            }
            if (EPI == 2) {
                o.x = gelu_exact(o.x); o.y = gelu_exact(o.y);
                o.z = gelu_exact(o.z); o.w = gelu_exact(o.w);
            }
            *(float4*)&C[(size_t)m*N + n] = o;
        }
    }
}

// ---------------- flash attention: 64q x 64k tiles, D=64 ---------------------
// grid: (S/64, H, B), 256 threads (16x16 of 4x4 fragments)
// smem: Qs[64][68], KP[64][68] (K tile then P tile), Vs[64][68]
#define AST 68
#define ATTN_SMEM (3*64*AST*4)

__global__ void __launch_bounds__(256)
attn_k(const float* __restrict__ q, const float* __restrict__ k,
       const float* __restrict__ v, const int* __restrict__ mask,
       float* __restrict__ ctx) {
    extern __shared__ float sm[];
    float* Qs = sm;
    float* KP = sm + 64*AST;
    float* Vs = sm + 2*64*AST;

    int qt = blockIdx.x, h = blockIdx.y, b = blockIdx.z;
    int tid = threadIdx.x, tx = tid & 15, ty = tid >> 4;
    int q0 = qt * 64;

    int lr = tid >> 2;               // load row 0..63
    int lc = (tid & 3) * 16;         // 16 floats (4x float4) per thread

    const float* qbase = q + ((size_t)(b*Ss) + q0) * Ee + h*Dd;
    #pragma unroll
    for (int u = 0; u < 4; u++)
        *(float4*)&Qs[lr*AST + lc + u*4] = *(const float4*)(qbase + (size_t)lr*Ee + lc + u*4);

    float mrow[4], lrow[4], o[4][4];
    #pragma unroll
    for (int i = 0; i < 4; i++) {
        mrow[i] = -1e30f; lrow[i] = 0.f;
        #pragma unroll
        for (int j = 0; j < 4; j++) o[i][j] = 0.f;
    }

    for (int t = 0; t < Ss/64; t++) {
        int k0 = t * 64;
        const float* kbase = k + ((size_t)(b*Ss) + k0) * Ee + h*Dd;
        const float* vbase = v + ((size_t)(b*Ss) + k0) * Ee + h*Dd;
        __syncthreads();   // previous tile's P/V reads done
        #pragma unroll
        for (int u = 0; u < 4; u++) {
            *(float4*)&KP[lr*AST + lc + u*4] = *(const float4*)(kbase + (size_t)lr*Ee + lc + u*4);
            *(float4*)&Vs[lr*AST + lc + u*4] = *(const float4*)(vbase + (size_t)lr*Ee + lc + u*4);
        }
        __syncthreads();

        // S = Q K^T  (4x4 per thread)
        float s[4][4];
        #pragma unroll
        for (int i = 0; i < 4; i++)
            #pragma unroll
            for (int j = 0; j < 4; j++) s[i][j] = 0.f;

        #pragma unroll 4
        for (int d4 = 0; d4 < 16; d4++) {
            float4 qv[4], kv[4];
            #pragma unroll
            for (int i = 0; i < 4; i++) qv[i] = *(const float4*)&Qs[(4*ty+i)*AST + d4*4];
            #pragma unroll
            for (int j = 0; j < 4; j++) kv[j] = *(const float4*)&KP[(4*tx+j)*AST + d4*4];
            #pragma unroll
            for (int i = 0; i < 4; i++)
                #pragma unroll
                for (int j = 0; j < 4; j++)
                    s[i][j] += qv[i].x*kv[j].x + qv[i].y*kv[j].y
                             + qv[i].z*kv[j].z + qv[i].w*kv[j].w;
        }

        // scale + mask  (scale = 1/sqrt(E) = 1/32)
        int mk[4];
        #pragma unroll
        for (int j = 0; j < 4; j++) mk[j] = mask[b*Ss + k0 + 4*tx + j];
        #pragma unroll
        for (int i = 0; i < 4; i++)
            #pragma unroll
            for (int j = 0; j < 4; j++)
                s[i][j] = mk[j] ? s[i][j] * 0.03125f : -1e9f;

        // online softmax update
        #pragma unroll
        for (int i = 0; i < 4; i++) {
            float rm = fmaxf(fmaxf(s[i][0], s[i][1]), fmaxf(s[i][2], s[i][3]));
            #pragma unroll
            for (int off = 1; off < 16; off <<= 1)
                rm = fmaxf(rm, __shfl_xor_sync(0xffffffffu, rm, off));
            float mnew  = fmaxf(mrow[i], rm);
            float alpha = __expf(mrow[i] - mnew);
            mrow[i] = mnew;
            float rs = 0.f;
            #pragma unroll
            for (int j = 0; j < 4; j++) { s[i][j] = __expf(s[i][j] - mnew); rs += s[i][j]; }
            #pragma unroll
            for (int off = 1; off < 16; off <<= 1)
                rs += __shfl_xor_sync(0xffffffffu, rs, off);
            lrow[i] = lrow[i]*alpha + rs;
            #pragma unroll
            for (int j = 0; j < 4; j++) o[i][j] *= alpha;
        }

        __syncthreads();   // done reading KP as K-tile
        #pragma unroll
        for (int i = 0; i < 4; i++)
            #pragma unroll
            for (int j = 0; j < 4; j++)
                KP[(4*ty+i)*AST + 4*tx + j] = s[i][j];   // store P
        __syncthreads();

        // O += P @ V
        #pragma unroll 4
        for (int k4 = 0; k4 < 16; k4++) {
            float4 vv0 = *(const float4*)&Vs[(k4*4+0)*AST + 4*tx];
            float4 vv1 = *(const float4*)&Vs[(k4*4+1)*AST + 4*tx];
            float4 vv2 = *(const float4*)&Vs[(k4*4+2)*AST + 4*tx];
            float4 vv3 = *(const float4*)&Vs[(k4*4+3)*AST + 4*tx];
            #pragma unroll
            for (int i = 0; i < 4; i++) {
                float4 pv = *(const float4*)&KP[(4*ty+i)*AST + k4*4];
                o[i][0] += pv.x*vv0.x + pv.y*vv1.x + pv.z*vv2.x + pv.w*vv3.x;
                o[i][1] += pv.x*vv0.y + pv.y*vv1.y + pv.z*vv2.y + pv.w*vv3.y;
                o[i][2] += pv.x*vv0.z + pv.y*vv1.z + pv.z*vv2.z + pv.w*vv3.z;
                o[i][3] += pv.x*vv0.w + pv.y*vv1.w + pv.z*vv2.w + pv.w*vv3.w;
            }
        }
    }

    // normalize and write ctx (head-interleaved [B*S, E] = concat-heads layout)
    #pragma unroll
    for (int i = 0; i < 4; i++) {
        float inv = 1.f / lrow[i];
        int row = b*Ss + q0 + 4*ty + i;
        float4 ov;
        ov.x = o[i][0]*inv; ov.y = o[i][1]*inv; ov.z = o[i][2]*inv; ov.w = o[i][3]*inv;
        *(float4*)&ctx[(size_t)row*Ee + h*Dd + 4*tx] = ov;
    }
}

// ---------------- launch ------------------------------------------------------
extern "C" void kernel_launch(void* const* d_in, const int* in_sizes, int n_in,
                              void* d_out, int out_size) {
    const float* I      = (const float*)d_in[0];
    const float* x      = (const float*)d_in[1];
    const int*   mask   = (const int*)  d_in[2];
    const float* wq     = (const float*)d_in[3];
    const float* bq     = (const float*)d_in[4];
    const float* wk     = (const float*)d_in[5];
    const float* bk     = (const float*)d_in[6];
    const float* wv     = (const float*)d_in[7];
    const float* bv     = (const float*)d_in[8];
    const float* w_proj = (const float*)d_in[9];
    const float* b_proj = (const float*)d_in[10];
    const float* g1     = (const float*)d_in[11];
    const float* be1    = (const float*)d_in[12];
    const float* g2     = (const float*)d_in[13];
    const float* be2    = (const float*)d_in[14];
    const float* w1     = (const float*)d_in[15];
    const float* b1     = (const float*)d_in[16];
    const float* w2     = (const float*)d_in[17];
    const float* b2     = (const float*)d_in[18];
    float* out = (float*)d_out;

    float *xn, *qb, *kb, *vb, *ctx, *hb, *h2, *ffa, *wq2, *wk2, *wv2;
    cudaGetSymbolAddress((void**)&xn,  g_xn);
    cudaGetSymbolAddress((void**)&qb,  g_q);
    cudaGetSymbolAddress((void**)&kb,  g_k);
    cudaGetSymbolAddress((void**)&vb,  g_v);
    cudaGetSymbolAddress((void**)&ctx, g_ctx);
    cudaGetSymbolAddress((void**)&hb,  g_h);
    cudaGetSymbolAddress((void**)&h2,  g_h2);
    cudaGetSymbolAddress((void**)&ffa, g_ffa);
    cudaGetSymbolAddress((void**)&wq2, g_wq2);
    cudaGetSymbolAddress((void**)&wk2, g_wk2);
    cudaGetSymbolAddress((void**)&wv2, g_wv2);

    cudaFuncSetAttribute(attn_k, cudaFuncAttributeMaxDynamicSharedMemorySize, ATTN_SMEM);

    int pe = (Ee*Ee + 255) / 256;
    pack_w<<<pe, 256>>>(wq, wq2);
    pack_w<<<pe, 256>>>(wk, wk2);
    pack_w<<<pe, 256>>>(wv, wv2);

    ln_k<<<MM, 256>>>(x, g1, be1, xn);

    dim3 gE(Ee/128, MM/128);         // N=1024 GEMMs
    sgemm_k<0><<<gE, 256>>>(I,  wq2, bq, nullptr, qb, MM, Ee, Ee);
    sgemm_k<0><<<gE, 256>>>(xn, wk2, bk, nullptr, kb, MM, Ee, Ee);
    sgemm_k<0><<<gE, 256>>>(xn, wv2, bv, nullptr, vb, MM, Ee, Ee);

    attn_k<<<dim3(Ss/64, Hh, Bb), 256, ATTN_SMEM>>>(qb, kb, vb, mask, ctx);

    sgemm_k<1><<<gE, 256>>>(ctx, w_proj, b_proj, xn, hb, MM, Ee, Ee);

    ln_k<<<MM, 256>>>(hb, g2, be2, h2);

    dim3 gF1(4*Ee/128, MM/128);      // N=4096
    sgemm_k<2><<<gF1, 256>>>(h2, w1, b1, nullptr, ffa, MM, 4*Ee, Ee);
    sgemm_k<1><<<gE, 256>>>(ffa, w2, b2, h2, out, MM, Ee, 4*Ee);
}

// round 3
// speedup vs baseline: 1.4471x; 1.4471x over previous
#include <cuda_runtime.h>
#include <math.h>
#include <stdint.h>

#define Bb 2
#define Ss 2048
#define Ee 1024
#define Hh 16
#define Dd 64
#define MM (Bb*Ss)          // 4096 rows
#define EPSv 1e-5f

// ---------------- scratch (static device globals; no allocation) -------------
__device__ float g_xn [MM*Ee];
__device__ float g_q  [MM*Ee];
__device__ float g_k  [MM*Ee];
__device__ float g_v  [MM*Ee];
__device__ float g_ctx[MM*Ee];
__device__ float g_h  [MM*Ee];
__device__ float g_h2 [MM*Ee];
__device__ float g_ffa[MM*4*Ee];
__device__ float g_wqT[Ee*Ee];      // [N,K] K-major
__device__ float g_wkT[Ee*Ee];
__device__ float g_wvT[Ee*Ee];
__device__ float g_wpT[Ee*Ee];
__device__ float g_w1T[4*Ee*Ee];    // [4E, E]
__device__ float g_w2T[Ee*4*Ee];    // [E, 4E]

// ---------------- weight repack: [H,E,D] -> [N=H*D, K=E] K-major --------------
__global__ void pack_wT(const float* __restrict__ w, float* __restrict__ o) {
    int i = blockIdx.x * blockDim.x + threadIdx.x;   // over E*E, i = n*E + e
    if (i < Ee*Ee) {
        int n = i / Ee, e = i % Ee;
        int h = n / Dd, d = n % Dd;
        o[i] = w[(h*Ee + e)*Dd + d];
    }
}

// ---------------- tiled transpose: in [R,C] -> out [C,R] ----------------------
__global__ void transpose_k(const float* __restrict__ in, float* __restrict__ out,
                            int R, int C) {
    __shared__ float t[32][33];
    int c = blockIdx.x*32 + threadIdx.x;
    int r0 = blockIdx.y*32;
    #pragma unroll
    for (int i = 0; i < 4; i++)
        t[threadIdx.y + i*8][threadIdx.x] = in[(size_t)(r0 + threadIdx.y + i*8)*C + c];
    __syncthreads();
    int c2 = r0 + threadIdx.x;
    int r2 = blockIdx.x*32;
    #pragma unroll
    for (int i = 0; i < 4; i++)
        out[(size_t)(r2 + threadIdx.y + i*8)*R + c2] = t[threadIdx.x][threadIdx.y + i*8];
}

// ---------------- LayerNorm: one block per row of 1024 -----------------------
__global__ void ln_k(const float* __restrict__ x, const float* __restrict__ g,
                     const float* __restrict__ b, float* __restrict__ y) {
    int row = blockIdx.x;
    int t = threadIdx.x;                // 256 threads, float4 each
    float4 v = ((const float4*)(x + (size_t)row*Ee))[t];
    float s  = v.x + v.y + v.z + v.w;
    float sq = v.x*v.x + v.y*v.y + v.z*v.z + v.w*v.w;
    __shared__ float sh1[8], sh2[8];
    #pragma unroll
    for (int o = 16; o > 0; o >>= 1) {
        s  += __shfl_xor_sync(0xffffffffu, s,  o);
        sq += __shfl_xor_sync(0xffffffffu, sq, o);
    }
    int lane = t & 31, w = t >> 5;
    if (lane == 0) { sh1[w] = s; sh2[w] = sq; }
    __syncthreads();
    s = 0.f; sq = 0.f;
    #pragma unroll
    for (int i = 0; i < 8; i++) { s += sh1[i]; sq += sh2[i]; }
    float mu  = s  * (1.f/Ee);
    float var = sq * (1.f/Ee) - mu*mu;
    float rs  = rsqrtf(var + EPSv);
    float4 gv = ((const float4*)g)[t];
    float4 bv = ((const float4*)b)[t];
    float4 o4;
    o4.x = (v.x - mu)*rs*gv.x + bv.x;
    o4.y = (v.y - mu)*rs*gv.y + bv.y;
    o4.z = (v.z - mu)*rs*gv.z + bv.z;
    o4.w = (v.w - mu)*rs*gv.w + bv.w;
    ((float4*)(y + (size_t)row*Ee))[t] = o4;
}

// =================== mma.sync tf32 GEMM: 128x128 tile, Kc=32 ==================
// C[M,N] = A[M,K] @ Bt[N,K]^T (+bias, EPI: 0 bias / 1 bias+res / 2 bias+GELU)
__device__ __forceinline__ float gelu_exact(float x) {
    return 0.5f * x * (1.0f + erff(x * 0.7071067811865476f));
}
__device__ __forceinline__ uint32_t f2tf32(float x) {
    uint32_t r;
    asm("cvt.rna.tf32.f32 %0, %1;" : "=r"(r) : "f"(x));
    return r;
}
__device__ __forceinline__ void mma_tf32(float* d, const uint32_t* a, const uint32_t* b) {
    asm volatile(
        "mma.sync.aligned.m16n8k8.row.col.f32.tf32.tf32.f32 "
        "{%0,%1,%2,%3}, {%4,%5,%6,%7}, {%8,%9}, {%0,%1,%2,%3};"
        : "+f"(d[0]), "+f"(d[1]), "+f"(d[2]), "+f"(d[3])
        : "r"(a[0]), "r"(a[1]), "r"(a[2]), "r"(a[3]), "r"(b[0]), "r"(b[1]));
}

#define KC 32
#define LDT 36                       // smem row stride (floats), pad vs bank conflicts
#define GSMEM (2*128*LDT*4)          // A tile + B tile (single stage)

template<int EPI>
__global__ void __launch_bounds__(256)
tc_gemm(const float* __restrict__ A, const float* __restrict__ Bt,
        const float* __restrict__ bias, const float* __restrict__ res,
        float* __restrict__ C, int M, int N, int K) {
    extern __shared__ float sm[];
    float* sA = sm;                  // [128][LDT]
    float* sB = sm + 128*LDT;        // [128][LDT]

    const int tid  = threadIdx.x;
    const int lane = tid & 31, wid = tid >> 5;
    const int wm = wid & 1, wn = wid >> 1;          // warp grid 2(M) x 4(N)
    const int row0 = blockIdx.y * 128, col0 = blockIdx.x * 128;

    // loader mapping: 2 threads per row, 16 floats each
    const int lrow = tid >> 1;
    const int lcg  = (tid & 1) * 16;
    const float* Arow = A  + (size_t)(row0 + lrow) * K + lcg;
    const float* Brow = Bt + (size_t)(col0 + lrow) * K + lcg;

    float acc[4][4][4];
    #pragma unroll
    for (int i = 0; i < 4; i++)
        #pragma unroll
        for (int j = 0; j < 4; j++)
            #pragma unroll
            for (int c = 0; c < 4; c++) acc[i][j][c] = 0.f;

    const int NK = K / KC;
    float4 pa[4], pb[4];
    // prefetch chunk 0
    #pragma unroll
    for (int u = 0; u < 4; u++) {
        pa[u] = *(const float4*)(Arow + u*4);
        pb[u] = *(const float4*)(Brow + u*4);
    }

    const int fr = lane >> 2;        // fragment row/col within 8
    const int fk = lane & 3;

    for (int kc = 0; kc < NK; kc++) {
        // store prefetched chunk with tf32 rounding
        #pragma unroll
        for (int u = 0; u < 4; u++) {
            float* da = sA + lrow*LDT + lcg + u*4;
            float* db = sB + lrow*LDT + lcg + u*4;
            da[0] = __uint_as_float(f2tf32(pa[u].x));
            da[1] = __uint_as_float(f2tf32(pa[u].y));
            da[2] = __uint_as_float(f2tf32(pa[u].z));
            da[3] = __uint_as_float(f2tf32(pa[u].w));
            db[0] = __uint_as_float(f2tf32(pb[u].x));
            db[1] = __uint_as_float(f2tf32(pb[u].y));
            db[2] = __uint_as_float(f2tf32(pb[u].z));
            db[3] = __uint_as_float(f2tf32(pb[u].w));
        }
        __syncthreads();

        // prefetch next chunk (global loads overlap compute below)
        if (kc + 1 < NK) {
            #pragma unroll
            for (int u = 0; u < 4; u++) {
                pa[u] = *(const float4*)(Arow + (kc+1)*KC + u*4);
                pb[u] = *(const float4*)(Brow + (kc+1)*KC + u*4);
            }
        }

        // compute: 4 k-steps of m16n8k8
        #pragma unroll
        for (int ks = 0; ks < 4; ks++) {
            int k0 = ks * 8;
            uint32_t af[4][4], bf[4][2];
            #pragma unroll
            for (int mi = 0; mi < 4; mi++) {
                const float* ap = sA + (wm*64 + mi*16 + fr)*LDT + k0 + fk;
                af[mi][0] = __float_as_uint(ap[0]);
                af[mi][1] = __float_as_uint(ap[8*LDT]);
                af[mi][2] = __float_as_uint(ap[4]);
                af[mi][3] = __float_as_uint(ap[8*LDT + 4]);
            }
            #pragma unroll
            for (int ni = 0; ni < 4; ni++) {
                const float* bp = sB + (wn*32 + ni*8 + fr)*LDT + k0 + fk;
                bf[ni][0] = __float_as_uint(bp[0]);
                bf[ni][1] = __float_as_uint(bp[4]);
            }
            #pragma unroll
            for (int mi = 0; mi < 4; mi++)
                #pragma unroll
                for (int ni = 0; ni < 4; ni++)
                    mma_tf32(acc[mi][ni], af[mi], bf[ni]);
        }
        __syncthreads();
    }

    // epilogue
    #pragma unroll
    for (int mi = 0; mi < 4; mi++) {
        int m = row0 + wm*64 + mi*16 + fr;
        #pragma unroll
        for (int ni = 0; ni < 4; ni++) {
            int n = col0 + wn*32 + ni*8 + 2*fk;
            float b0 = bias[n], b1 = bias[n+1];
            float v0 = acc[mi][ni][0] + b0;
            float v1 = acc[mi][ni][1] + b1;
            float v2 = acc[mi][ni][2] + b0;
            float v3 = acc[mi][ni][3] + b1;
            if (EPI == 1) {
                float2 r0 = *(const float2*)&res[(size_t)m*N + n];
                float2 r1 = *(const float2*)&res[(size_t)(m+8)*N + n];
                v0 += r0.x; v1 += r0.y; v2 += r1.x; v3 += r1.y;
            }
            if (EPI == 2) {
                v0 = gelu_exact(v0); v1 = gelu_exact(v1);
                v2 = gelu_exact(v2); v3 = gelu_exact(v3);
            }
            *(float2*)&C[(size_t)m*N + n]     = make_float2(v0, v1);
            *(float2*)&C[(size_t)(m+8)*N + n] = make_float2(v2, v3);
        }
    }
}

// ---------------- flash attention: 64q x 64k tiles, D=64 ---------------------
#define AST 68
#define ATTN_SMEM (3*64*AST*4)

__global__ void __launch_bounds__(256)
attn_k(const float* __restrict__ q, const float* __restrict__ k,
       const float* __restrict__ v, const int* __restrict__ mask,
       float* __restrict__ ctx) {
    extern __shared__ float sm[];
    float* Qs = sm;
    float* KP = sm + 64*AST;
    float* Vs = sm + 2*64*AST;

    int qt = blockIdx.x, h = blockIdx.y, b = blockIdx.z;
    int tid = threadIdx.x, tx = tid & 15, ty = tid >> 4;
    int q0 = qt * 64;

    int lr = tid >> 2;               // load row 0..63
    int lc = (tid & 3) * 16;         // 16 floats (4x float4) per thread

    const float* qbase = q + ((size_t)(b*Ss) + q0) * Ee + h*Dd;
    #pragma unroll
    for (int u = 0; u < 4; u++)
        *(float4*)&Qs[lr*AST + lc + u*4] = *(const float4*)(qbase + (size_t)lr*Ee + lc + u*4);

    float mrow[4], lrow[4], o[4][4];
    #pragma unroll
    for (int i = 0; i < 4; i++) {
        mrow[i] = -1e30f; lrow[i] = 0.f;
        #pragma unroll
        for (int j = 0; j < 4; j++) o[i][j] = 0.f;
    }

    for (int t = 0; t < Ss/64; t++) {
        int k0 = t * 64;
        const float* kbase = k + ((size_t)(b*Ss) + k0) * Ee + h*Dd;
        const float* vbase = v + ((size_t)(b*Ss) + k0) * Ee + h*Dd;
        __syncthreads();   // previous tile's P/V reads done
        #pragma unroll
        for (int u = 0; u < 4; u++) {
            *(float4*)&KP[lr*AST + lc + u*4] = *(const float4*)(kbase + (size_t)lr*Ee + lc + u*4);
            *(float4*)&Vs[lr*AST + lc + u*4] = *(const float4*)(vbase + (size_t)lr*Ee + lc + u*4);
        }
        __syncthreads();

        float s[4][4];
        #pragma unroll
        for (int i = 0; i < 4; i++)
            #pragma unroll
            for (int j = 0; j < 4; j++) s[i][j] = 0.f;

        #pragma unroll 4
        for (int d4 = 0; d4 < 16; d4++) {
            float4 qv[4], kv[4];
            #pragma unroll
            for (int i = 0; i < 4; i++) qv[i] = *(const float4*)&Qs[(4*ty+i)*AST + d4*4];
            #pragma unroll
            for (int j = 0; j < 4; j++) kv[j] = *(const float4*)&KP[(4*tx+j)*AST + d4*4];
            #pragma unroll
            for (int i = 0; i < 4; i++)
                #pragma unroll
                for (int j = 0; j < 4; j++)
                    s[i][j] += qv[i].x*kv[j].x + qv[i].y*kv[j].y
                             + qv[i].z*kv[j].z + qv[i].w*kv[j].w;
        }

        int mk[4];
        #pragma unroll
        for (int j = 0; j < 4; j++) mk[j] = mask[b*Ss + k0 + 4*tx + j];
        #pragma unroll
        for (int i = 0; i < 4; i++)
            #pragma unroll
            for (int j = 0; j < 4; j++)
                s[i][j] = mk[j] ? s[i][j] * 0.03125f : -1e9f;

        #pragma unroll
        for (int i = 0; i < 4; i++) {
            float rm = fmaxf(fmaxf(s[i][0], s[i][1]), fmaxf(s[i][2], s[i][3]));
            #pragma unroll
            for (int off = 1; off < 16; off <<= 1)
                rm = fmaxf(rm, __shfl_xor_sync(0xffffffffu, rm, off));
            float mnew  = fmaxf(mrow[i], rm);
            float alpha = __expf(mrow[i] - mnew);
            mrow[i] = mnew;
            float rs = 0.f;
            #pragma unroll
            for (int j = 0; j < 4; j++) { s[i][j] = __expf(s[i][j] - mnew); rs += s[i][j]; }
            #pragma unroll
            for (int off = 1; off < 16; off <<= 1)
                rs += __shfl_xor_sync(0xffffffffu, rs, off);
            lrow[i] = lrow[i]*alpha + rs;
            #pragma unroll
            for (int j = 0; j < 4; j++) o[i][j] *= alpha;
        }

        __syncthreads();
        #pragma unroll
        for (int i = 0; i < 4; i++)
            #pragma unroll
            for (int j = 0; j < 4; j++)
                KP[(4*ty+i)*AST + 4*tx + j] = s[i][j];
        __syncthreads();

        #pragma unroll 4
        for (int k4 = 0; k4 < 16; k4++) {
            float4 vv0 = *(const float4*)&Vs[(k4*4+0)*AST + 4*tx];
            float4 vv1 = *(const float4*)&Vs[(k4*4+1)*AST + 4*tx];
            float4 vv2 = *(const float4*)&Vs[(k4*4+2)*AST + 4*tx];
            float4 vv3 = *(const float4*)&Vs[(k4*4+3)*AST + 4*tx];
            #pragma unroll
            for (int i = 0; i < 4; i++) {
                float4 pv = *(const float4*)&KP[(4*ty+i)*AST + k4*4];
                o[i][0] += pv.x*vv0.x + pv.y*vv1.x + pv.z*vv2.x + pv.w*vv3.x;
                o[i][1] += pv.x*vv0.y + pv.y*vv1.y + pv.z*vv2.y + pv.w*vv3.y;
                o[i][2] += pv.x*vv0.z + pv.y*vv1.z + pv.z*vv2.z + pv.w*vv3.z;
                o[i][3] += pv.x*vv0.w + pv.y*vv1.w + pv.z*vv2.w + pv.w*vv3.w;
            }
        }
    }

    #pragma unroll
    for (int i = 0; i < 4; i++) {
        float inv = 1.f / lrow[i];
        int row = b*Ss + q0 + 4*ty + i;
        float4 ov;
        ov.x = o[i][0]*inv; ov.y = o[i][1]*inv; ov.z = o[i][2]*inv; ov.w = o[i][3]*inv;
        *(float4*)&ctx[(size_t)row*Ee + h*Dd + 4*tx] = ov;
    }
}

// ---------------- launch ------------------------------------------------------
extern "C" void kernel_launch(void* const* d_in, const int* in_sizes, int n_in,
                              void* d_out, int out_size) {
    const float* I      = (const float*)d_in[0];
    const float* x      = (const float*)d_in[1];
    const int*   mask   = (const int*)  d_in[2];
    const float* wq     = (const float*)d_in[3];
    const float* bq     = (const float*)d_in[4];
    const float* wk     = (const float*)d_in[5];
    const float* bk     = (const float*)d_in[6];
    const float* wv     = (const float*)d_in[7];
    const float* bv     = (const float*)d_in[8];
    const float* w_proj = (const float*)d_in[9];
    const float* b_proj = (const float*)d_in[10];
    const float* g1     = (const float*)d_in[11];
    const float* be1    = (const float*)d_in[12];
    const float* g2     = (const float*)d_in[13];
    const float* be2    = (const float*)d_in[14];
    const float* w1     = (const float*)d_in[15];
    const float* b1     = (const float*)d_in[16];
    const float* w2     = (const float*)d_in[17];
    const float* b2     = (const float*)d_in[18];
    float* out = (float*)d_out;

    float *xn, *qb, *kb, *vb, *ctx, *hb, *h2, *ffa;
    float *wqT, *wkT, *wvT, *wpT, *w1T, *w2T;
    cudaGetSymbolAddress((void**)&xn,  g_xn);
    cudaGetSymbolAddress((void**)&qb,  g_q);
    cudaGetSymbolAddress((void**)&kb,  g_k);
    cudaGetSymbolAddress((void**)&vb,  g_v);
    cudaGetSymbolAddress((void**)&ctx, g_ctx);
    cudaGetSymbolAddress((void**)&hb,  g_h);
    cudaGetSymbolAddress((void**)&h2,  g_h2);
    cudaGetSymbolAddress((void**)&ffa, g_ffa);
    cudaGetSymbolAddress((void**)&wqT, g_wqT);
    cudaGetSymbolAddress((void**)&wkT, g_wkT);
    cudaGetSymbolAddress((void**)&wvT, g_wvT);
    cudaGetSymbolAddress((void**)&wpT, g_wpT);
    cudaGetSymbolAddress((void**)&w1T, g_w1T);
    cudaGetSymbolAddress((void**)&w2T, g_w2T);

    cudaFuncSetAttribute(attn_k, cudaFuncAttributeMaxDynamicSharedMemorySize, ATTN_SMEM);
    cudaFuncSetAttribute(tc_gemm<0>, cudaFuncAttributeMaxDynamicSharedMemorySize, GSMEM);
    cudaFuncSetAttribute(tc_gemm<1>, cudaFuncAttributeMaxDynamicSharedMemorySize, GSMEM);
    cudaFuncSetAttribute(tc_gemm<2>, cudaFuncAttributeMaxDynamicSharedMemorySize, GSMEM);

    // weight prep: per-head pack -> [N,K]; dense transposes -> [N,K]
    int pe = (Ee*Ee + 255) / 256;
    pack_wT<<<pe, 256>>>(wq, wqT);
    pack_wT<<<pe, 256>>>(wk, wkT);
    pack_wT<<<pe, 256>>>(wv, wvT);
    transpose_k<<<dim3(Ee/32,   Ee/32),   dim3(32,8)>>>(w_proj, wpT, Ee,   Ee);
    transpose_k<<<dim3(4*Ee/32, Ee/32),   dim3(32,8)>>>(w1,     w1T, Ee,   4*Ee);
    transpose_k<<<dim3(Ee/32,   4*Ee/32), dim3(32,8)>>>(w2,     w2T, 4*Ee, Ee);

    ln_k<<<MM, 256>>>(x, g1, be1, xn);

    dim3 gE(Ee/128, MM/128);         // N=1024 GEMMs
    tc_gemm<0><<<gE, 256, GSMEM>>>(I,  wqT, bq, nullptr, qb, MM, Ee, Ee);
    tc_gemm<0><<<gE, 256, GSMEM>>>(xn, wkT, bk, nullptr, kb, MM, Ee, Ee);
    tc_gemm<0><<<gE, 256, GSMEM>>>(xn, wvT, bv, nullptr, vb, MM, Ee, Ee);

    attn_k<<<dim3(Ss/64, Hh, Bb), 256, ATTN_SMEM>>>(qb, kb, vb, mask, ctx);

    tc_gemm<1><<<gE, 256, GSMEM>>>(ctx, wpT, b_proj, xn, hb, MM, Ee, Ee);

    ln_k<<<MM, 256>>>(hb, g2, be2, h2);

    dim3 gF1(4*Ee/128, MM/128);      // N=4096
    tc_gemm<2><<<gF1, 256, GSMEM>>>(h2, w1T, b1, nullptr, ffa, MM, 4*Ee, Ee);
    tc_gemm<1><<<gE, 256, GSMEM>>>(ffa, w2T, b2, h2, out, MM, Ee, 4*Ee);
}

// round 4
// speedup vs baseline: 2.2580x; 1.5604x over previous
#include <cuda_runtime.h>
#include <math.h>
#include <stdint.h>

#define Bb 2
#define Ss 2048
#define Ee 1024
#define Hh 16
#define Dd 64
#define MM (Bb*Ss)          // 4096 rows
#define EPSv 1e-5f

// ---------------- scratch (static device globals; no allocation) -------------
__device__ float g_xn [MM*Ee];
__device__ float g_q  [MM*Ee];
__device__ float g_k  [MM*Ee];
__device__ float g_v  [MM*Ee];
__device__ float g_ctx[MM*Ee];
__device__ float g_h  [MM*Ee];
__device__ float g_h2 [MM*Ee];
__device__ float g_ffa[MM*4*Ee];
__device__ float g_wqT[Ee*Ee];      // [N,K] K-major
__device__ float g_wkT[Ee*Ee];
__device__ float g_wvT[Ee*Ee];
__device__ float g_wpT[Ee*Ee];
__device__ float g_w1T[4*Ee*Ee];    // [4E, E]
__device__ float g_w2T[Ee*4*Ee];    // [E, 4E]

// ---------------- common tf32 helpers ----------------------------------------
__device__ __forceinline__ uint32_t f2tf32(float x) {
    uint32_t r;
    asm("cvt.rna.tf32.f32 %0, %1;" : "=r"(r) : "f"(x));
    return r;
}
__device__ __forceinline__ float tf32f(float x) { return __uint_as_float(f2tf32(x)); }
__device__ __forceinline__ void mma_tf32(float* d, const uint32_t* a, const uint32_t* b) {
    asm volatile(
        "mma.sync.aligned.m16n8k8.row.col.f32.tf32.tf32.f32 "
        "{%0,%1,%2,%3}, {%4,%5,%6,%7}, {%8,%9}, {%0,%1,%2,%3};"
        : "+f"(d[0]), "+f"(d[1]), "+f"(d[2]), "+f"(d[3])
        : "r"(a[0]), "r"(a[1]), "r"(a[2]), "r"(a[3]), "r"(b[0]), "r"(b[1]));
}

// ---------------- weight repack: [H,E,D] -> [N=H*D, K=E] K-major --------------
__global__ void pack_wT(const float* __restrict__ w, float* __restrict__ o) {
    int i = blockIdx.x * blockDim.x + threadIdx.x;   // over E*E, i = n*E + e
    if (i < Ee*Ee) {
        int n = i / Ee, e = i % Ee;
        int h = n / Dd, d = n % Dd;
        o[i] = w[(h*Ee + e)*Dd + d];
    }
}

// ---------------- tiled transpose: in [R,C] -> out [C,R] ----------------------
__global__ void transpose_k(const float* __restrict__ in, float* __restrict__ out,
                            int R, int C) {
    __shared__ float t[32][33];
    int c = blockIdx.x*32 + threadIdx.x;
    int r0 = blockIdx.y*32;
    #pragma unroll
    for (int i = 0; i < 4; i++)
        t[threadIdx.y + i*8][threadIdx.x] = in[(size_t)(r0 + threadIdx.y + i*8)*C + c];
    __syncthreads();
    int c2 = r0 + threadIdx.x;
    int r2 = blockIdx.x*32;
    #pragma unroll
    for (int i = 0; i < 4; i++)
        out[(size_t)(r2 + threadIdx.y + i*8)*R + c2] = t[threadIdx.x][threadIdx.y + i*8];
}

// ---------------- LayerNorm: one block per row of 1024 -----------------------
__global__ void ln_k(const float* __restrict__ x, const float* __restrict__ g,
                     const float* __restrict__ b, float* __restrict__ y) {
    int row = blockIdx.x;
    int t = threadIdx.x;                // 256 threads, float4 each
    float4 v = ((const float4*)(x + (size_t)row*Ee))[t];
    float s  = v.x + v.y + v.z + v.w;
    float sq = v.x*v.x + v.y*v.y + v.z*v.z + v.w*v.w;
    __shared__ float sh1[8], sh2[8];
    #pragma unroll
    for (int o = 16; o > 0; o >>= 1) {
        s  += __shfl_xor_sync(0xffffffffu, s,  o);
        sq += __shfl_xor_sync(0xffffffffu, sq, o);
    }
    int lane = t & 31, w = t >> 5;
    if (lane == 0) { sh1[w] = s; sh2[w] = sq; }
    __syncthreads();
    s = 0.f; sq = 0.f;
    #pragma unroll
    for (int i = 0; i < 8; i++) { s += sh1[i]; sq += sh2[i]; }
    float mu  = s  * (1.f/Ee);
    float var = sq * (1.f/Ee) - mu*mu;
    float rs  = rsqrtf(var + EPSv);
    float4 gv = ((const float4*)g)[t];
    float4 bv = ((const float4*)b)[t];
    float4 o4;
    o4.x = (v.x - mu)*rs*gv.x + bv.x;
    o4.y = (v.y - mu)*rs*gv.y + bv.y;
    o4.z = (v.z - mu)*rs*gv.z + bv.z;
    o4.w = (v.w - mu)*rs*gv.w + bv.w;
    ((float4*)(y + (size_t)row*Ee))[t] = o4;
}

// =================== mma.sync tf32 GEMM: 128x128 tile, Kc=32 ==================
__device__ __forceinline__ float gelu_exact(float x) {
    return 0.5f * x * (1.0f + erff(x * 0.7071067811865476f));
}

#define KC 32
#define LDT 36                       // smem row stride (floats), pad vs bank conflicts
#define GSMEM (2*128*LDT*4)          // A tile + B tile (single stage)

template<int EPI>
__global__ void __launch_bounds__(256)
tc_gemm(const float* __restrict__ A, const float* __restrict__ Bt,
        const float* __restrict__ bias, const float* __restrict__ res,
        float* __restrict__ C, int M, int N, int K) {
    extern __shared__ float sm[];
    float* sA = sm;                  // [128][LDT]
    float* sB = sm + 128*LDT;        // [128][LDT]

    const int tid  = threadIdx.x;
    const int lane = tid & 31, wid = tid >> 5;
    const int wm = wid & 1, wn = wid >> 1;          // warp grid 2(M) x 4(N)
    const int row0 = blockIdx.y * 128, col0 = blockIdx.x * 128;

    const int lrow = tid >> 1;
    const int lcg  = (tid & 1) * 16;
    const float* Arow = A  + (size_t)(row0 + lrow) * K + lcg;
    const float* Brow = Bt + (size_t)(col0 + lrow) * K + lcg;

    float acc[4][4][4];
    #pragma unroll
    for (int i = 0; i < 4; i++)
        #pragma unroll
        for (int j = 0; j < 4; j++)
            #pragma unroll
            for (int c = 0; c < 4; c++) acc[i][j][c] = 0.f;

    const int NK = K / KC;
    float4 pa[4], pb[4];
    #pragma unroll
    for (int u = 0; u < 4; u++) {
        pa[u] = *(const float4*)(Arow + u*4);
        pb[u] = *(const float4*)(Brow + u*4);
    }

    const int fr = lane >> 2;
    const int fk = lane & 3;

    for (int kc = 0; kc < NK; kc++) {
        #pragma unroll
        for (int u = 0; u < 4; u++) {
            float* da = sA + lrow*LDT + lcg + u*4;
            float* db = sB + lrow*LDT + lcg + u*4;
            da[0] = tf32f(pa[u].x); da[1] = tf32f(pa[u].y);
            da[2] = tf32f(pa[u].z); da[3] = tf32f(pa[u].w);
            db[0] = tf32f(pb[u].x); db[1] = tf32f(pb[u].y);
            db[2] = tf32f(pb[u].z); db[3] = tf32f(pb[u].w);
        }
        __syncthreads();

        if (kc + 1 < NK) {
            #pragma unroll
            for (int u = 0; u < 4; u++) {
                pa[u] = *(const float4*)(Arow + (kc+1)*KC + u*4);
                pb[u] = *(const float4*)(Brow + (kc+1)*KC + u*4);
            }
        }

        #pragma unroll
        for (int ks = 0; ks < 4; ks++) {
            int k0 = ks * 8;
            uint32_t af[4][4], bf[4][2];
            #pragma unroll
            for (int mi = 0; mi < 4; mi++) {
                const float* ap = sA + (wm*64 + mi*16 + fr)*LDT + k0 + fk;
                af[mi][0] = __float_as_uint(ap[0]);
                af[mi][1] = __float_as_uint(ap[8*LDT]);
                af[mi][2] = __float_as_uint(ap[4]);
                af[mi][3] = __float_as_uint(ap[8*LDT + 4]);
            }
            #pragma unroll
            for (int ni = 0; ni < 4; ni++) {
                const float* bp = sB + (wn*32 + ni*8 + fr)*LDT + k0 + fk;
                bf[ni][0] = __float_as_uint(bp[0]);
                bf[ni][1] = __float_as_uint(bp[4]);
            }
            #pragma unroll
            for (int mi = 0; mi < 4; mi++)
                #pragma unroll
                for (int ni = 0; ni < 4; ni++)
                    mma_tf32(acc[mi][ni], af[mi], bf[ni]);
        }
        __syncthreads();
    }

    #pragma unroll
    for (int mi = 0; mi < 4; mi++) {
        int m = row0 + wm*64 + mi*16 + fr;
        #pragma unroll
        for (int ni = 0; ni < 4; ni++) {
            int n = col0 + wn*32 + ni*8 + 2*fk;
            float b0 = bias[n], b1 = bias[n+1];
            float v0 = acc[mi][ni][0] + b0;
            float v1 = acc[mi][ni][1] + b1;
            float v2 = acc[mi][ni][2] + b0;
            float v3 = acc[mi][ni][3] + b1;
            if (EPI == 1) {
                float2 r0 = *(const float2*)&res[(size_t)m*N + n];
                float2 r1 = *(const float2*)&res[(size_t)(m+8)*N + n];
                v0 += r0.x; v1 += r0.y; v2 += r1.x; v3 += r1.y;
            }
            if (EPI == 2) {
                v0 = gelu_exact(v0); v1 = gelu_exact(v1);
                v2 = gelu_exact(v2); v3 = gelu_exact(v3);
            }
            *(float2*)&C[(size_t)m*N + n]     = make_float2(v0, v1);
            *(float2*)&C[(size_t)(m+8)*N + n] = make_float2(v2, v3);
        }
    }
}

// ============= tf32 mma flash attention: 128q x 64k tiles, D=64 ==============
// 8 warps; each warp owns 16 query rows end-to-end (S, softmax, P, O).
#define LQ 68                    // Qs/Ks/Ps stride (floats)
#define LV 65                    // Vt stride (floats), odd to break conflicts
#define ATTN_SMEM ((128*LQ + 64*LQ + 64*LV + 128*LQ) * 4)

__global__ void __launch_bounds__(256)
attn_tc(const float* __restrict__ q, const float* __restrict__ k,
        const float* __restrict__ v, const int* __restrict__ mask,
        float* __restrict__ ctx) {
    extern __shared__ float sm[];
    float* Qs = sm;                  // [128][LQ]  (tf32)
    float* Ks = Qs + 128*LQ;         // [64][LQ]   (tf32, [key][d])
    float* Vt = Ks + 64*LQ;          // [64][LV]   (tf32, [d][key])
    float* Ps = Vt + 64*LV;          // [128][LQ]  (tf32)

    const int tid = threadIdx.x, lane = tid & 31, wid = tid >> 5;
    const int fr = lane >> 2, fk = lane & 3;
    const int h = blockIdx.y, b = blockIdx.z;
    const int q0 = blockIdx.x * 128;
    const int r0 = wid*16 + fr;      // CTA-local query rows owned by this thread
    const int r1 = r0 + 8;

    // load Q tile (128 x 64), tf32-rounded
    {
        int lrow = tid >> 1, half = (tid & 1) * 32;
        const float* qb = q + ((size_t)(b*Ss) + q0 + lrow)*Ee + h*Dd + half;
        float* dst = Qs + lrow*LQ + half;
        #pragma unroll
        for (int u = 0; u < 8; u++) {
            float4 w = *(const float4*)(qb + u*4);
            dst[u*4+0] = tf32f(w.x); dst[u*4+1] = tf32f(w.y);
            dst[u*4+2] = tf32f(w.z); dst[u*4+3] = tf32f(w.w);
        }
    }

    float acc_o[8][4];
    #pragma unroll
    for (int ni = 0; ni < 8; ni++)
        #pragma unroll
        for (int c = 0; c < 4; c++) acc_o[ni][c] = 0.f;
    float m0 = -1e30f, m1 = -1e30f, l0 = 0.f, l1 = 0.f;

    const int klr = tid >> 2, kc = (tid & 3) * 16;

    for (int kt = 0; kt < Ss/64; kt++) {
        int k0 = kt * 64;
        __syncthreads();             // protect Ks/Vt from previous iteration reads
        {
            const float* kb = k + ((size_t)(b*Ss) + k0 + klr)*Ee + h*Dd + kc;
            const float* vb = v + ((size_t)(b*Ss) + k0 + klr)*Ee + h*Dd + kc;
            float* kd = Ks + klr*LQ + kc;
            #pragma unroll
            for (int u = 0; u < 4; u++) {
                float4 w = *(const float4*)(kb + u*4);
                kd[u*4+0] = tf32f(w.x); kd[u*4+1] = tf32f(w.y);
                kd[u*4+2] = tf32f(w.z); kd[u*4+3] = tf32f(w.w);
                float4 x2 = *(const float4*)(vb + u*4);
                Vt[(kc+u*4+0)*LV + klr] = tf32f(x2.x);
                Vt[(kc+u*4+1)*LV + klr] = tf32f(x2.y);
                Vt[(kc+u*4+2)*LV + klr] = tf32f(x2.z);
                Vt[(kc+u*4+3)*LV + klr] = tf32f(x2.w);
            }
        }
        __syncthreads();

        // S = Q K^T : warp rows r0/r1, 8 n-fragments, 8 k-steps
        float accs[8][4];
        #pragma unroll
        for (int ni = 0; ni < 8; ni++)
            #pragma unroll
            for (int c = 0; c < 4; c++) accs[ni][c] = 0.f;

        #pragma unroll
        for (int ks = 0; ks < 8; ks++) {
            uint32_t af[4];
            const float* ap = Qs + r0*LQ + ks*8 + fk;
            af[0] = __float_as_uint(ap[0]);
            af[1] = __float_as_uint(ap[8*LQ]);
            af[2] = __float_as_uint(ap[4]);
            af[3] = __float_as_uint(ap[8*LQ + 4]);
            #pragma unroll
            for (int ni = 0; ni < 8; ni++) {
                uint32_t bf[2];
                const float* bp = Ks + (ni*8 + fr)*LQ + ks*8 + fk;
                bf[0] = __float_as_uint(bp[0]);
                bf[1] = __float_as_uint(bp[4]);
                mma_tf32(accs[ni], af, bf);
            }
        }

        // scale + mask
        float rm0 = -1e30f, rm1 = -1e30f;
        #pragma unroll
        for (int ni = 0; ni < 8; ni++) {
            int col = b*Ss + k0 + ni*8 + 2*fk;
            int mk0 = mask[col], mk1 = mask[col+1];
            accs[ni][0] = mk0 ? accs[ni][0]*0.03125f : -1e9f;
            accs[ni][1] = mk1 ? accs[ni][1]*0.03125f : -1e9f;
            accs[ni][2] = mk0 ? accs[ni][2]*0.03125f : -1e9f;
            accs[ni][3] = mk1 ? accs[ni][3]*0.03125f : -1e9f;
            rm0 = fmaxf(rm0, fmaxf(accs[ni][0], accs[ni][1]));
            rm1 = fmaxf(rm1, fmaxf(accs[ni][2], accs[ni][3]));
        }
        rm0 = fmaxf(rm0, __shfl_xor_sync(0xffffffffu, rm0, 1));
        rm0 = fmaxf(rm0, __shfl_xor_sync(0xffffffffu, rm0, 2));
        rm1 = fmaxf(rm1, __shfl_xor_sync(0xffffffffu, rm1, 1));
        rm1 = fmaxf(rm1, __shfl_xor_sync(0xffffffffu, rm1, 2));

        float mn0 = fmaxf(m0, rm0), mn1 = fmaxf(m1, rm1);
        float a0 = __expf(m0 - mn0), a1 = __expf(m1 - mn1);
        m0 = mn0; m1 = mn1;

        float rs0 = 0.f, rs1 = 0.f;
        #pragma unroll
        for (int ni = 0; ni < 8; ni++) {
            accs[ni][0] = __expf(accs[ni][0] - mn0);
            accs[ni][1] = __expf(accs[ni][1] - mn0);
            accs[ni][2] = __expf(accs[ni][2] - mn1);
            accs[ni][3] = __expf(accs[ni][3] - mn1);
            rs0 += accs[ni][0] + accs[ni][1];
            rs1 += accs[ni][2] + accs[ni][3];
        }
        rs0 += __shfl_xor_sync(0xffffffffu, rs0, 1);
        rs0 += __shfl_xor_sync(0xffffffffu, rs0, 2);
        rs1 += __shfl_xor_sync(0xffffffffu, rs1, 1);
        rs1 += __shfl_xor_sync(0xffffffffu, rs1, 2);
        l0 = l0*a0 + rs0;
        l1 = l1*a1 + rs1;

        #pragma unroll
        for (int ni = 0; ni < 8; ni++) {
            acc_o[ni][0] *= a0; acc_o[ni][1] *= a0;
            acc_o[ni][2] *= a1; acc_o[ni][3] *= a1;
        }

        // P -> smem (tf32)
        #pragma unroll
        for (int ni = 0; ni < 8; ni++) {
            *(float2*)&Ps[r0*LQ + ni*8 + 2*fk] =
                make_float2(tf32f(accs[ni][0]), tf32f(accs[ni][1]));
            *(float2*)&Ps[r1*LQ + ni*8 + 2*fk] =
                make_float2(tf32f(accs[ni][2]), tf32f(accs[ni][3]));
        }
        __syncwarp();

        // O += P @ V  (A = P rows r0/r1, B = Vt[d][key])
        #pragma unroll
        for (int ks = 0; ks < 8; ks++) {
            uint32_t af[4];
            const float* ap = Ps + r0*LQ + ks*8 + fk;
            af[0] = __float_as_uint(ap[0]);
            af[1] = __float_as_uint(ap[8*LQ]);
            af[2] = __float_as_uint(ap[4]);
            af[3] = __float_as_uint(ap[8*LQ + 4]);
            #pragma unroll
            for (int ni = 0; ni < 8; ni++) {
                uint32_t bf[2];
                const float* bp = Vt + (ni*8 + fr)*LV + ks*8 + fk;
                bf[0] = __float_as_uint(bp[0]);
                bf[1] = __float_as_uint(bp[4]);
                mma_tf32(acc_o[ni], af, bf);
            }
        }
    }

    // normalize + write (head-interleaved concat layout)
    float i0 = 1.f / l0, i1 = 1.f / l1;
    size_t grow0 = (size_t)(b*Ss + q0 + r0) * Ee + h*Dd;
    size_t grow1 = (size_t)(b*Ss + q0 + r1) * Ee + h*Dd;
    #pragma unroll
    for (int ni = 0; ni < 8; ni++) {
        int col = ni*8 + 2*fk;
        *(float2*)&ctx[grow0 + col] = make_float2(acc_o[ni][0]*i0, acc_o[ni][1]*i0);
        *(float2*)&ctx[grow1 + col] = make_float2(acc_o[ni][2]*i1, acc_o[ni][3]*i1);
    }
}

// ---------------- launch ------------------------------------------------------
extern "C" void kernel_launch(void* const* d_in, const int* in_sizes, int n_in,
                              void* d_out, int out_size) {
    const float* I      = (const float*)d_in[0];
    const float* x      = (const float*)d_in[1];
    const int*   mask   = (const int*)  d_in[2];
    const float* wq     = (const float*)d_in[3];
    const float* bq     = (const float*)d_in[4];
    const float* wk     = (const float*)d_in[5];
    const float* bk     = (const float*)d_in[6];
    const float* wv     = (const float*)d_in[7];
    const float* bv     = (const float*)d_in[8];
    const float* w_proj = (const float*)d_in[9];
    const float* b_proj = (const float*)d_in[10];
    const float* g1     = (const float*)d_in[11];
    const float* be1    = (const float*)d_in[12];
    const float* g2     = (const float*)d_in[13];
    const float* be2    = (const float*)d_in[14];
    const float* w1     = (const float*)d_in[15];
    const float* b1     = (const float*)d_in[16];
    const float* w2     = (const float*)d_in[17];
    const float* b2     = (const float*)d_in[18];
    float* out = (float*)d_out;

    float *xn, *qb, *kb, *vb, *ctx, *hb, *h2, *ffa;
    float *wqT, *wkT, *wvT, *wpT, *w1T, *w2T;
    cudaGetSymbolAddress((void**)&xn,  g_xn);
    cudaGetSymbolAddress((void**)&qb,  g_q);
    cudaGetSymbolAddress((void**)&kb,  g_k);
    cudaGetSymbolAddress((void**)&vb,  g_v);
    cudaGetSymbolAddress((void**)&ctx, g_ctx);
    cudaGetSymbolAddress((void**)&hb,  g_h);
    cudaGetSymbolAddress((void**)&h2,  g_h2);
    cudaGetSymbolAddress((void**)&ffa, g_ffa);
    cudaGetSymbolAddress((void**)&wqT, g_wqT);
    cudaGetSymbolAddress((void**)&wkT, g_wkT);
    cudaGetSymbolAddress((void**)&wvT, g_wvT);
    cudaGetSymbolAddress((void**)&wpT, g_wpT);
    cudaGetSymbolAddress((void**)&w1T, g_w1T);
    cudaGetSymbolAddress((void**)&w2T, g_w2T);

    cudaFuncSetAttribute(attn_tc, cudaFuncAttributeMaxDynamicSharedMemorySize, ATTN_SMEM);
    cudaFuncSetAttribute(tc_gemm<0>, cudaFuncAttributeMaxDynamicSharedMemorySize, GSMEM);
    cudaFuncSetAttribute(tc_gemm<1>, cudaFuncAttributeMaxDynamicSharedMemorySize, GSMEM);
    cudaFuncSetAttribute(tc_gemm<2>, cudaFuncAttributeMaxDynamicSharedMemorySize, GSMEM);

    // weight prep: per-head pack -> [N,K]; dense transposes -> [N,K]
    int pe = (Ee*Ee + 255) / 256;
    pack_wT<<<pe, 256>>>(wq, wqT);
    pack_wT<<<pe, 256>>>(wk, wkT);
    pack_wT<<<pe, 256>>>(wv, wvT);
    transpose_k<<<dim3(Ee/32,   Ee/32),   dim3(32,8)>>>(w_proj, wpT, Ee,   Ee);
    transpose_k<<<dim3(4*Ee/32, Ee/32),   dim3(32,8)>>>(w1,     w1T, Ee,   4*Ee);
    transpose_k<<<dim3(Ee/32,   4*Ee/32), dim3(32,8)>>>(w2,     w2T, 4*Ee, Ee);

    ln_k<<<MM, 256>>>(x, g1, be1, xn);

    dim3 gE(Ee/128, MM/128);         // N=1024 GEMMs
    tc_gemm<0><<<gE, 256, GSMEM>>>(I,  wqT, bq, nullptr, qb, MM, Ee, Ee);
    tc_gemm<0><<<gE, 256, GSMEM>>>(xn, wkT, bk, nullptr, kb, MM, Ee, Ee);
    tc_gemm<0><<<gE, 256, GSMEM>>>(xn, wvT, bv, nullptr, vb, MM, Ee, Ee);

    attn_tc<<<dim3(Ss/128, Hh, Bb), 256, ATTN_SMEM>>>(qb, kb, vb, mask, ctx);

    tc_gemm<1><<<gE, 256, GSMEM>>>(ctx, wpT, b_proj, xn, hb, MM, Ee, Ee);

    ln_k<<<MM, 256>>>(hb, g2, be2, h2);

    dim3 gF1(4*Ee/128, MM/128);      // N=4096
    tc_gemm<2><<<gF1, 256, GSMEM>>>(h2, w1T, b1, nullptr, ffa, MM, 4*Ee, Ee);
    tc_gemm<1><<<gE, 256, GSMEM>>>(ffa, w2T, b2, h2, out, MM, Ee, 4*Ee);
}

// round 5
// speedup vs baseline: 2.7194x; 1.2043x over previous
#include <cuda_runtime.h>
#include <math.h>
#include <stdint.h>

#define Bb 2
#define Ss 2048
#define Ee 1024
#define Hh 16
#define Dd 64
#define MM (Bb*Ss)          // 4096 rows
#define EPSv 1e-5f

// ---------------- scratch (static device globals; no allocation) -------------
__device__ float g_Ir [MM*Ee];      // tf32-rounded I
__device__ float g_xn [MM*Ee];
__device__ float g_q  [MM*Ee];
__device__ float g_k  [MM*Ee];
__device__ float g_v  [MM*Ee];
__device__ float g_ctx[MM*Ee];
__device__ float g_h  [MM*Ee];
__device__ float g_h2 [MM*Ee];
__device__ float g_ffa[MM*4*Ee];
__device__ float g_wqT[Ee*Ee];      // [N,K] K-major, tf32-rounded
__device__ float g_wkT[Ee*Ee];
__device__ float g_wvT[Ee*Ee];
__device__ float g_wpT[Ee*Ee];
__device__ float g_w1T[4*Ee*Ee];    // [4E, E]
__device__ float g_w2T[Ee*4*Ee];    // [E, 4E]

// ---------------- helpers -----------------------------------------------------
__device__ __forceinline__ uint32_t smem_u32(const void* p) {
    uint32_t a;
    asm("{ .reg .u64 t; cvta.to.shared.u64 t, %1; cvt.u32.u64 %0, t; }"
        : "=r"(a) : "l"(p));
    return a;
}
__device__ __forceinline__ uint32_t f2tf32(float x) {
    uint32_t r;
    asm("cvt.rna.tf32.f32 %0, %1;" : "=r"(r) : "f"(x));
    return r;
}
__device__ __forceinline__ float tf32f(float x) { return __uint_as_float(f2tf32(x)); }
__device__ __forceinline__ void mma_tf32(float* d, const uint32_t* a, const uint32_t* b) {
    asm volatile(
        "mma.sync.aligned.m16n8k8.row.col.f32.tf32.tf32.f32 "
        "{%0,%1,%2,%3}, {%4,%5,%6,%7}, {%8,%9}, {%0,%1,%2,%3};"
        : "+f"(d[0]), "+f"(d[1]), "+f"(d[2]), "+f"(d[3])
        : "r"(a[0]), "r"(a[1]), "r"(a[2]), "r"(a[3]), "r"(b[0]), "r"(b[1]));
}
__device__ __forceinline__ void ldm_x4(uint32_t* r, uint32_t addr) {
    asm volatile("ldmatrix.sync.aligned.m8n8.x4.shared.b16 {%0,%1,%2,%3}, [%4];"
        : "=r"(r[0]), "=r"(r[1]), "=r"(r[2]), "=r"(r[3]) : "r"(addr));
}
#define CP_ASYNC16(dst, src) \
    asm volatile("cp.async.ca.shared.global [%0], [%1], 16;" :: "r"(dst), "l"(src))
#define CP_COMMIT() asm volatile("cp.async.commit_group;" ::: "memory")
#define CP_WAIT(n)  asm volatile("cp.async.wait_group %0;" :: "n"(n) : "memory")

// ---------------- one-shot tf32 rounding of I --------------------------------
__global__ void round_k(const float* __restrict__ in, float* __restrict__ out) {
    int i = blockIdx.x * blockDim.x + threadIdx.x;
    float4 v = ((const float4*)in)[i];
    float4 o;
    o.x = tf32f(v.x); o.y = tf32f(v.y); o.z = tf32f(v.z); o.w = tf32f(v.w);
    ((float4*)out)[i] = o;
}

// ---------------- weight repack: [H,E,D] -> [N=H*D, K=E], tf32-rounded --------
__global__ void pack_wT(const float* __restrict__ w, float* __restrict__ o) {
    int i = blockIdx.x * blockDim.x + threadIdx.x;   // i = n*E + e
    if (i < Ee*Ee) {
        int n = i / Ee, e = i % Ee;
        int h = n / Dd, d = n % Dd;
        o[i] = tf32f(w[(h*Ee + e)*Dd + d]);
    }
}

// ---------------- tiled transpose + tf32 round: in [R,C] -> out [C,R] ---------
__global__ void transpose_k(const float* __restrict__ in, float* __restrict__ out,
                            int R, int C) {
    __shared__ float t[32][33];
    int c = blockIdx.x*32 + threadIdx.x;
    int r0 = blockIdx.y*32;
    #pragma unroll
    for (int i = 0; i < 4; i++)
        t[threadIdx.y + i*8][threadIdx.x] = in[(size_t)(r0 + threadIdx.y + i*8)*C + c];
    __syncthreads();
    int c2 = r0 + threadIdx.x;
    int r2 = blockIdx.x*32;
    #pragma unroll
    for (int i = 0; i < 4; i++)
        out[(size_t)(r2 + threadIdx.y + i*8)*R + c2] = tf32f(t[threadIdx.x][threadIdx.y + i*8]);
}

// ---------------- LayerNorm (outputs tf32-rounded) ----------------------------
__global__ void ln_k(const float* __restrict__ x, const float* __restrict__ g,
                     const float* __restrict__ b, float* __restrict__ y) {
    int row = blockIdx.x;
    int t = threadIdx.x;
    float4 v = ((const float4*)(x + (size_t)row*Ee))[t];
    float s  = v.x + v.y + v.z + v.w;
    float sq = v.x*v.x + v.y*v.y + v.z*v.z + v.w*v.w;
    __shared__ float sh1[8], sh2[8];
    #pragma unroll
    for (int o = 16; o > 0; o >>= 1) {
        s  += __shfl_xor_sync(0xffffffffu, s,  o);
        sq += __shfl_xor_sync(0xffffffffu, sq, o);
    }
    int lane = t & 31, w = t >> 5;
    if (lane == 0) { sh1[w] = s; sh2[w] = sq; }
    __syncthreads();
    s = 0.f; sq = 0.f;
    #pragma unroll
    for (int i = 0; i < 8; i++) { s += sh1[i]; sq += sh2[i]; }
    float mu  = s  * (1.f/Ee);
    float var = sq * (1.f/Ee) - mu*mu;
    float rs  = rsqrtf(var + EPSv);
    float4 gv = ((const float4*)g)[t];
    float4 bv = ((const float4*)b)[t];
    float4 o4;
    o4.x = tf32f((v.x - mu)*rs*gv.x + bv.x);
    o4.y = tf32f((v.y - mu)*rs*gv.y + bv.y);
    o4.z = tf32f((v.z - mu)*rs*gv.z + bv.z);
    o4.w = tf32f((v.w - mu)*rs*gv.w + bv.w);
    ((float4*)(y + (size_t)row*Ee))[t] = o4;
}

// ====== tf32 GEMM: 128x128 tile, Kc=32, cp.async 2-stage, ldmatrix ===========
// EPI: 0 bias / 1 bias+res / 2 bias+GELU ;  RND: round output to tf32
__device__ __forceinline__ float gelu_exact(float x) {
    return 0.5f * x * (1.0f + erff(x * 0.7071067811865476f));
}

#define LDT 36                        // smem row stride (floats)
#define STAGE_BYTES (128*LDT*4)       // one tile (18432 B)
#define STAGE_PAIR  (2*STAGE_BYTES)   // A+B per stage
#define GSMEM (2*STAGE_PAIR)          // 2 stages

template<int EPI, int RND>
__global__ void __launch_bounds__(256, 2)
tc_gemm(const float* __restrict__ A, const float* __restrict__ Bt,
        const float* __restrict__ bias, const float* __restrict__ res,
        float* __restrict__ C, int M, int N, int K) {
    extern __shared__ float sm[];
    const int tid = threadIdx.x, lane = tid & 31, wid = tid >> 5;
    const int wm = wid & 1, wn = wid >> 1;          // warp grid 2(M) x 4(N)
    const int row0 = blockIdx.y * 128, col0 = blockIdx.x * 128;
    const int fr = lane >> 2, fk = lane & 3;

    const uint32_t sbase = smem_u32(sm);

    // loader mapping: 2 threads per row, 16 floats (4x cp.async 16B) each
    const int lrow = tid >> 1, lcg = (tid & 1) * 16;
    const float* Arow = A  + (size_t)(row0 + lrow) * K + lcg;
    const float* Brow = Bt + (size_t)(col0 + lrow) * K + lcg;
    const uint32_t sd = sbase + (uint32_t)(lrow*LDT + lcg) * 4;

    // ldmatrix per-thread addresses (byte offsets from stage base)
    const int r8 = lane & 7, g = lane >> 3;
    uint32_t a_off[4], b_off[2];
    #pragma unroll
    for (int mi = 0; mi < 4; mi++)
        a_off[mi] = sbase +
            (uint32_t)(((wm*64 + mi*16 + (g&1)*8 + r8)*LDT) + (g>>1)*4) * 4;
    #pragma unroll
    for (int n2 = 0; n2 < 2; n2++)
        b_off[n2] = sbase + STAGE_BYTES +
            (uint32_t)(((wn*32 + n2*16 + (g>>1)*8 + r8)*LDT) + (g&1)*4) * 4;

    float acc[4][4][4];
    #pragma unroll
    for (int i = 0; i < 4; i++)
        #pragma unroll
        for (int j = 0; j < 4; j++)
            #pragma unroll
            for (int c = 0; c < 4; c++) acc[i][j][c] = 0.f;

    const int NK = K >> 5;

    // prologue: stage 0
    {
        uint32_t da = sd, db = sd + STAGE_BYTES;
        #pragma unroll
        for (int u = 0; u < 4; u++) {
            CP_ASYNC16(da + u*16, Arow + u*4);
            CP_ASYNC16(db + u*16, Brow + u*4);
        }
        CP_COMMIT();
    }

    for (int kc = 0; kc < NK; kc++) {
        int s = kc & 1;
        if (kc + 1 < NK) {
            uint32_t da = sd + (s^1)*STAGE_PAIR, db = da + STAGE_BYTES;
            const float* ga = Arow + (kc+1)*32;
            const float* gb = Brow + (kc+1)*32;
            #pragma unroll
            for (int u = 0; u < 4; u++) {
                CP_ASYNC16(da + u*16, ga + u*4);
                CP_ASYNC16(db + u*16, gb + u*4);
            }
            CP_COMMIT();
            CP_WAIT(1);
        } else {
            CP_WAIT(0);
        }
        __syncthreads();

        uint32_t stb = (uint32_t)(s * STAGE_PAIR);
        #pragma unroll
        for (int ks = 0; ks < 4; ks++) {
            uint32_t af[4][4], bb[2][4];
            #pragma unroll
            for (int mi = 0; mi < 4; mi++)
                ldm_x4(af[mi], a_off[mi] + stb + ks*32);
            #pragma unroll
            for (int n2 = 0; n2 < 2; n2++)
                ldm_x4(bb[n2], b_off[n2] + stb + ks*32);
            #pragma unroll
            for (int mi = 0; mi < 4; mi++)
                #pragma unroll
                for (int ni = 0; ni < 4; ni++)
                    mma_tf32(acc[mi][ni], af[mi], &bb[ni>>1][(ni&1)*2]);
        }
        __syncthreads();
    }

    // epilogue
    #pragma unroll
    for (int mi = 0; mi < 4; mi++) {
        int m = row0 + wm*64 + mi*16 + fr;
        #pragma unroll
        for (int ni = 0; ni < 4; ni++) {
            int n = col0 + wn*32 + ni*8 + 2*fk;
            float b0 = bias[n], b1 = bias[n+1];
            float v0 = acc[mi][ni][0] + b0;
            float v1 = acc[mi][ni][1] + b1;
            float v2 = acc[mi][ni][2] + b0;
            float v3 = acc[mi][ni][3] + b1;
            if (EPI == 1) {
                float2 r0 = *(const float2*)&res[(size_t)m*N + n];
                float2 r1 = *(const float2*)&res[(size_t)(m+8)*N + n];
                v0 += r0.x; v1 += r0.y; v2 += r1.x; v3 += r1.y;
            }
            if (EPI == 2) {
                v0 = gelu_exact(v0); v1 = gelu_exact(v1);
                v2 = gelu_exact(v2); v3 = gelu_exact(v3);
            }
            if (RND) {
                v0 = tf32f(v0); v1 = tf32f(v1); v2 = tf32f(v2); v3 = tf32f(v3);
            }
            *(float2*)&C[(size_t)m*N + n]     = make_float2(v0, v1);
            *(float2*)&C[(size_t)(m+8)*N + n] = make_float2(v2, v3);
        }
    }
}

// ============= tf32 mma flash attention: 128q x 64k tiles, D=64 ==============
// q/k/v arrive tf32-rounded; loaders are plain copies.
#define LQ 68
#define LV 65
#define ATTN_SMEM ((128*LQ + 64*LQ + 64*LV + 128*LQ) * 4)

__global__ void __launch_bounds__(256)
attn_tc(const float* __restrict__ q, const float* __restrict__ k,
        const float* __restrict__ v, const int* __restrict__ mask,
        float* __restrict__ ctx) {
    extern __shared__ float sm[];
    float* Qs = sm;                  // [128][LQ]
    float* Ks = Qs + 128*LQ;         // [64][LQ]   ([key][d])
    float* Vt = Ks + 64*LQ;          // [64][LV]   ([d][key])
    float* Ps = Vt + 64*LV;          // [128][LQ]

    const int tid = threadIdx.x, lane = tid & 31, wid = tid >> 5;
    const int fr = lane >> 2, fk = lane & 3;
    const int h = blockIdx.y, b = blockIdx.z;
    const int q0 = blockIdx.x * 128;
    const int r0 = wid*16 + fr;
    const int r1 = r0 + 8;

    {
        int lrow = tid >> 1, half = (tid & 1) * 32;
        const float* qb = q + ((size_t)(b*Ss) + q0 + lrow)*Ee + h*Dd + half;
        float* dst = Qs + lrow*LQ + half;
        #pragma unroll
        for (int u = 0; u < 8; u++)
            *(float4*)(dst + u*4) = *(const float4*)(qb + u*4);
    }

    float acc_o[8][4];
    #pragma unroll
    for (int ni = 0; ni < 8; ni++)
        #pragma unroll
        for (int c = 0; c < 4; c++) acc_o[ni][c] = 0.f;
    float m0 = -1e30f, m1 = -1e30f, l0 = 0.f, l1 = 0.f;

    const int klr = tid >> 2, kc = (tid & 3) * 16;

    for (int kt = 0; kt < Ss/64; kt++) {
        int k0 = kt * 64;
        __syncthreads();
        {
            const float* kb = k + ((size_t)(b*Ss) + k0 + klr)*Ee + h*Dd + kc;
            const float* vb = v + ((size_t)(b*Ss) + k0 + klr)*Ee + h*Dd + kc;
            float* kd = Ks + klr*LQ + kc;
            #pragma unroll
            for (int u = 0; u < 4; u++) {
                *(float4*)(kd + u*4) = *(const float4*)(kb + u*4);
                float4 x2 = *(const float4*)(vb + u*4);
                Vt[(kc+u*4+0)*LV + klr] = x2.x;
                Vt[(kc+u*4+1)*LV + klr] = x2.y;
                Vt[(kc+u*4+2)*LV + klr] = x2.z;
                Vt[(kc+u*4+3)*LV + klr] = x2.w;
            }
        }
        __syncthreads();

        float accs[8][4];
        #pragma unroll
        for (int ni = 0; ni < 8; ni++)
            #pragma unroll
            for (int c = 0; c < 4; c++) accs[ni][c] = 0.f;

        #pragma unroll
        for (int ks = 0; ks < 8; ks++) {
            uint32_t af[4];
            const float* ap = Qs + r0*LQ + ks*8 + fk;
            af[0] = __float_as_uint(ap[0]);
            af[1] = __float_as_uint(ap[8*LQ]);
            af[2] = __float_as_uint(ap[4]);
            af[3] = __float_as_uint(ap[8*LQ + 4]);
            #pragma unroll
            for (int ni = 0; ni < 8; ni++) {
                uint32_t bf[2];
                const float* bp = Ks + (ni*8 + fr)*LQ + ks*8 + fk;
                bf[0] = __float_as_uint(bp[0]);
                bf[1] = __float_as_uint(bp[4]);
                mma_tf32(accs[ni], af, bf);
            }
        }

        float rm0 = -1e30f, rm1 = -1e30f;
        #pragma unroll
        for (int ni = 0; ni < 8; ni++) {
            int col = b*Ss + k0 + ni*8 + 2*fk;
            int mk0 = mask[col], mk1 = mask[col+1];
            accs[ni][0] = mk0 ? accs[ni][0]*0.03125f : -1e9f;
            accs[ni][1] = mk1 ? accs[ni][1]*0.03125f : -1e9f;
            accs[ni][2] = mk0 ? accs[ni][2]*0.03125f : -1e9f;
            accs[ni][3] = mk1 ? accs[ni][3]*0.03125f : -1e9f;
            rm0 = fmaxf(rm0, fmaxf(accs[ni][0], accs[ni][1]));
            rm1 = fmaxf(rm1, fmaxf(accs[ni][2], accs[ni][3]));
        }
        rm0 = fmaxf(rm0, __shfl_xor_sync(0xffffffffu, rm0, 1));
        rm0 = fmaxf(rm0, __shfl_xor_sync(0xffffffffu, rm0, 2));
        rm1 = fmaxf(rm1, __shfl_xor_sync(0xffffffffu, rm1, 1));
        rm1 = fmaxf(rm1, __shfl_xor_sync(0xffffffffu, rm1, 2));

        float mn0 = fmaxf(m0, rm0), mn1 = fmaxf(m1, rm1);
        float a0 = __expf(m0 - mn0), a1 = __expf(m1 - mn1);
        m0 = mn0; m1 = mn1;

        float rs0 = 0.f, rs1 = 0.f;
        #pragma unroll
        for (int ni = 0; ni < 8; ni++) {
            accs[ni][0] = __expf(accs[ni][0] - mn0);
            accs[ni][1] = __expf(accs[ni][1] - mn0);
            accs[ni][2] = __expf(accs[ni][2] - mn1);
            accs[ni][3] = __expf(accs[ni][3] - mn1);
            rs0 += accs[ni][0] + accs[ni][1];
            rs1 += accs[ni][2] + accs[ni][3];
        }
        rs0 += __shfl_xor_sync(0xffffffffu, rs0, 1);
        rs0 += __shfl_xor_sync(0xffffffffu, rs0, 2);
        rs1 += __shfl_xor_sync(0xffffffffu, rs1, 1);
        rs1 += __shfl_xor_sync(0xffffffffu, rs1, 2);
        l0 = l0*a0 + rs0;
        l1 = l1*a1 + rs1;

        #pragma unroll
        for (int ni = 0; ni < 8; ni++) {
            acc_o[ni][0] *= a0; acc_o[ni][1] *= a0;
            acc_o[ni][2] *= a1; acc_o[ni][3] *= a1;
        }

        #pragma unroll
        for (int ni = 0; ni < 8; ni++) {
            *(float2*)&Ps[r0*LQ + ni*8 + 2*fk] =
                make_float2(tf32f(accs[ni][0]), tf32f(accs[ni][1]));
            *(float2*)&Ps[r1*LQ + ni*8 + 2*fk] =
                make_float2(tf32f(accs[ni][2]), tf32f(accs[ni][3]));
        }
        __syncwarp();

        #pragma unroll
        for (int ks = 0; ks < 8; ks++) {
            uint32_t af[4];
            const float* ap = Ps + r0*LQ + ks*8 + fk;
            af[0] = __float_as_uint(ap[0]);
            af[1] = __float_as_uint(ap[8*LQ]);
            af[2] = __float_as_uint(ap[4]);
            af[3] = __float_as_uint(ap[8*LQ + 4]);
            #pragma unroll
            for (int ni = 0; ni < 8; ni++) {
                uint32_t bf[2];
                const float* bp = Vt + (ni*8 + fr)*LV + ks*8 + fk;
                bf[0] = __float_as_uint(bp[0]);
                bf[1] = __float_as_uint(bp[4]);
                mma_tf32(acc_o[ni], af, bf);
            }
        }
    }

    float i0 = 1.f / l0, i1 = 1.f / l1;
    size_t grow0 = (size_t)(b*Ss + q0 + r0) * Ee + h*Dd;
    size_t grow1 = (size_t)(b*Ss + q0 + r1) * Ee + h*Dd;
    #pragma unroll
    for (int ni = 0; ni < 8; ni++) {
        int col = ni*8 + 2*fk;
        *(float2*)&ctx[grow0 + col] =
            make_float2(tf32f(acc_o[ni][0]*i0), tf32f(acc_o[ni][1]*i0));
        *(float2*)&ctx[grow1 + col] =
            make_float2(tf32f(acc_o[ni][2]*i1), tf32f(acc_o[ni][3]*i1));
    }
}

// ---------------- launch ------------------------------------------------------
extern "C" void kernel_launch(void* const* d_in, const int* in_sizes, int n_in,
                              void* d_out, int out_size) {
    const float* I      = (const float*)d_in[0];
    const float* x      = (const float*)d_in[1];
    const int*   mask   = (const int*)  d_in[2];
    const float* wq     = (const float*)d_in[3];
    const float* bq     = (const float*)d_in[4];
    const float* wk     = (const float*)d_in[5];
    const float* bk     = (const float*)d_in[6];
    const float* wv     = (const float*)d_in[7];
    const float* bv     = (const float*)d_in[8];
    const float* w_proj = (const float*)d_in[9];
    const float* b_proj = (const float*)d_in[10];
    const float* g1     = (const float*)d_in[11];
    const float* be1    = (const float*)d_in[12];
    const float* g2     = (const float*)d_in[13];
    const float* be2    = (const float*)d_in[14];
    const float* w1     = (const float*)d_in[15];
    const float* b1     = (const float*)d_in[16];
    const float* w2     = (const float*)d_in[17];
    const float* b2     = (const float*)d_in[18];
    float* out = (float*)d_out;

    float *Ir, *xn, *qb, *kb, *vb, *ctx, *hb, *h2, *ffa;
    float *wqT, *wkT, *wvT, *wpT, *w1T, *w2T;
    cudaGetSymbolAddress((void**)&Ir,  g_Ir);
    cudaGetSymbolAddress((void**)&xn,  g_xn);
    cudaGetSymbolAddress((void**)&qb,  g_q);
    cudaGetSymbolAddress((void**)&kb,  g_k);
    cudaGetSymbolAddress((void**)&vb,  g_v);
    cudaGetSymbolAddress((void**)&ctx, g_ctx);
    cudaGetSymbolAddress((void**)&hb,  g_h);
    cudaGetSymbolAddress((void**)&h2,  g_h2);
    cudaGetSymbolAddress((void**)&ffa, g_ffa);
    cudaGetSymbolAddress((void**)&wqT, g_wqT);
    cudaGetSymbolAddress((void**)&wkT, g_wkT);
    cudaGetSymbolAddress((void**)&wvT, g_wvT);
    cudaGetSymbolAddress((void**)&wpT, g_wpT);
    cudaGetSymbolAddress((void**)&w1T, g_w1T);
    cudaGetSymbolAddress((void**)&w2T, g_w2T);

    cudaFuncSetAttribute(attn_tc, cudaFuncAttributeMaxDynamicSharedMemorySize, ATTN_SMEM);
    cudaFuncSetAttribute(tc_gemm<0,1>, cudaFuncAttributeMaxDynamicSharedMemorySize, GSMEM);
    cudaFuncSetAttribute(tc_gemm<1,0>, cudaFuncAttributeMaxDynamicSharedMemorySize, GSMEM);
    cudaFuncSetAttribute(tc_gemm<2,1>, cudaFuncAttributeMaxDynamicSharedMemorySize, GSMEM);

    // weight prep (rounded to tf32)
    int pe = (Ee*Ee + 255) / 256;
    pack_wT<<<pe, 256>>>(wq, wqT);
    pack_wT<<<pe, 256>>>(wk, wkT);
    pack_wT<<<pe, 256>>>(wv, wvT);
    transpose_k<<<dim3(Ee/32,   Ee/32),   dim3(32,8)>>>(w_proj, wpT, Ee,   Ee);
    transpose_k<<<dim3(4*Ee/32, Ee/32),   dim3(32,8)>>>(w1,     w1T, Ee,   4*Ee);
    transpose_k<<<dim3(Ee/32,   4*Ee/32), dim3(32,8)>>>(w2,     w2T, 4*Ee, Ee);

    round_k<<<MM*Ee/4/256, 256>>>(I, Ir);
    ln_k<<<MM, 256>>>(x, g1, be1, xn);

    dim3 gE(Ee/128, MM/128);         // N=1024 GEMMs
    tc_gemm<0,1><<<gE, 256, GSMEM>>>(Ir, wqT, bq, nullptr, qb, MM, Ee, Ee);
    tc_gemm<0,1><<<gE, 256, GSMEM>>>(xn, wkT, bk, nullptr, kb, MM, Ee, Ee);
    tc_gemm<0,1><<<gE, 256, GSMEM>>>(xn, wvT, bv, nullptr, vb, MM, Ee, Ee);

    attn_tc<<<dim3(Ss/128, Hh, Bb), 256, ATTN_SMEM>>>(qb, kb, vb, mask, ctx);

    tc_gemm<1,0><<<gE, 256, GSMEM>>>(ctx, wpT, b_proj, xn, hb, MM, Ee, Ee);

    ln_k<<<MM, 256>>>(hb, g2, be2, h2);

    dim3 gF1(4*Ee/128, MM/128);      // N=4096
    tc_gemm<2,1><<<gF1, 256, GSMEM>>>(h2, w1T, b1, nullptr, ffa, MM, 4*Ee, Ee);
    tc_gemm<1,0><<<gE, 256, GSMEM>>>(ffa, w2T, b2, h2, out, MM, Ee, 4*Ee);
}

// round 6
// speedup vs baseline: 3.0133x; 1.1080x over previous
#include <cuda_runtime.h>
#include <math.h>
#include <stdint.h>

#define Bb 2
#define Ss 2048
#define Ee 1024
#define Hh 16
#define Dd 64
#define MM (Bb*Ss)          // 4096 rows
#define EPSv 1e-5f

// ---------------- scratch (static device globals; no allocation) -------------
__device__ float g_Ir [MM*Ee];      // tf32-rounded I
__device__ float g_xn [MM*Ee];
__device__ float g_q  [MM*Ee];
__device__ float g_k  [MM*Ee];
__device__ float g_v  [MM*Ee];
__device__ float g_ctx[MM*Ee];
__device__ float g_h  [MM*Ee];
__device__ float g_h2 [MM*Ee];
__device__ float g_ffa[MM*4*Ee];
__device__ float g_wqT[Ee*Ee];      // [N,K] K-major, tf32-rounded
__device__ float g_wkT[Ee*Ee];
__device__ float g_wvT[Ee*Ee];
__device__ float g_wpT[Ee*Ee];
__device__ float g_w1T[4*Ee*Ee];    // [4E, E]
__device__ float g_w2T[Ee*4*Ee];    // [E, 4E]

// ---------------- helpers -----------------------------------------------------
__device__ __forceinline__ uint32_t smem_u32(const void* p) {
    uint32_t a;
    asm("{ .reg .u64 t; cvta.to.shared.u64 t, %1; cvt.u32.u64 %0, t; }"
        : "=r"(a) : "l"(p));
    return a;
}
__device__ __forceinline__ uint32_t f2tf32(float x) {
    uint32_t r;
    asm("cvt.rna.tf32.f32 %0, %1;" : "=r"(r) : "f"(x));
    return r;
}
__device__ __forceinline__ float tf32f(float x) { return __uint_as_float(f2tf32(x)); }
__device__ __forceinline__ void mma_tf32(float* d, const uint32_t* a, const uint32_t* b) {
    asm volatile(
        "mma.sync.aligned.m16n8k8.row.col.f32.tf32.tf32.f32 "
        "{%0,%1,%2,%3}, {%4,%5,%6,%7}, {%8,%9}, {%0,%1,%2,%3};"
        : "+f"(d[0]), "+f"(d[1]), "+f"(d[2]), "+f"(d[3])
        : "r"(a[0]), "r"(a[1]), "r"(a[2]), "r"(a[3]), "r"(b[0]), "r"(b[1]));
}
__device__ __forceinline__ void ldm_x4(uint32_t* r, uint32_t addr) {
    asm volatile("ldmatrix.sync.aligned.m8n8.x4.shared.b16 {%0,%1,%2,%3}, [%4];"
        : "=r"(r[0]), "=r"(r[1]), "=r"(r[2]), "=r"(r[3]) : "r"(addr));
}
#define CP_ASYNC16(dst, src) \
    asm volatile("cp.async.ca.shared.global [%0], [%1], 16;" :: "r"(dst), "l"(src))
#define CP_COMMIT() asm volatile("cp.async.commit_group;" ::: "memory")
#define CP_WAIT(n)  asm volatile("cp.async.wait_group %0;" :: "n"(n) : "memory")

// ---------------- one-shot tf32 rounding of I --------------------------------
__global__ void round_k(const float* __restrict__ in, float* __restrict__ out) {
    int i = blockIdx.x * blockDim.x + threadIdx.x;
    float4 v = ((const float4*)in)[i];
    float4 o;
    o.x = tf32f(v.x); o.y = tf32f(v.y); o.z = tf32f(v.z); o.w = tf32f(v.w);
    ((float4*)out)[i] = o;
}

// ---------------- weight repack: [H,E,D] -> [N=H*D, K=E], tf32-rounded --------
__global__ void pack_wT(const float* __restrict__ w, float* __restrict__ o) {
    int i = blockIdx.x * blockDim.x + threadIdx.x;   // i = n*E + e
    if (i < Ee*Ee) {
        int n = i / Ee, e = i % Ee;
        int h = n / Dd, d = n % Dd;
        o[i] = tf32f(w[(h*Ee + e)*Dd + d]);
    }
}

// ---------------- tiled transpose + tf32 round: in [R,C] -> out [C,R] ---------
__global__ void transpose_k(const float* __restrict__ in, float* __restrict__ out,
                            int R, int C) {
    __shared__ float t[32][33];
    int c = blockIdx.x*32 + threadIdx.x;
    int r0 = blockIdx.y*32;
    #pragma unroll
    for (int i = 0; i < 4; i++)
        t[threadIdx.y + i*8][threadIdx.x] = in[(size_t)(r0 + threadIdx.y + i*8)*C + c];
    __syncthreads();
    int c2 = r0 + threadIdx.x;
    int r2 = blockIdx.x*32;
    #pragma unroll
    for (int i = 0; i < 4; i++)
        out[(size_t)(r2 + threadIdx.y + i*8)*R + c2] = tf32f(t[threadIdx.x][threadIdx.y + i*8]);
}

// ---------------- LayerNorm (outputs tf32-rounded) ----------------------------
__global__ void ln_k(const float* __restrict__ x, const float* __restrict__ g,
                     const float* __restrict__ b, float* __restrict__ y) {
    int row = blockIdx.x;
    int t = threadIdx.x;
    float4 v = ((const float4*)(x + (size_t)row*Ee))[t];
    float s  = v.x + v.y + v.z + v.w;
    float sq = v.x*v.x + v.y*v.y + v.z*v.z + v.w*v.w;
    __shared__ float sh1[8], sh2[8];
    #pragma unroll
    for (int o = 16; o > 0; o >>= 1) {
        s  += __shfl_xor_sync(0xffffffffu, s,  o);
        sq += __shfl_xor_sync(0xffffffffu, sq, o);
    }
    int lane = t & 31, w = t >> 5;
    if (lane == 0) { sh1[w] = s; sh2[w] = sq; }
    __syncthreads();
    s = 0.f; sq = 0.f;
    #pragma unroll
    for (int i = 0; i < 8; i++) { s += sh1[i]; sq += sh2[i]; }
    float mu  = s  * (1.f/Ee);
    float var = sq * (1.f/Ee) - mu*mu;
    float rs  = rsqrtf(var + EPSv);
    float4 gv = ((const float4*)g)[t];
    float4 bv = ((const float4*)b)[t];
    float4 o4;
    o4.x = tf32f((v.x - mu)*rs*gv.x + bv.x);
    o4.y = tf32f((v.y - mu)*rs*gv.y + bv.y);
    o4.z = tf32f((v.z - mu)*rs*gv.z + bv.z);
    o4.w = tf32f((v.w - mu)*rs*gv.w + bv.w);
    ((float4*)(y + (size_t)row*Ee))[t] = o4;
}

// ====== tf32 GEMM: 128x128 tile, Kc=32, cp.async 3-stage, ldmatrix ===========
__device__ __forceinline__ float gelu_exact(float x) {
    return 0.5f * x * (1.0f + erff(x * 0.7071067811865476f));
}

#define LDT 36                        // smem row stride (floats)
#define STAGE_BYTES (128*LDT*4)       // one tile (18432 B)
#define STAGE_PAIR  (2*STAGE_BYTES)   // A+B per stage (36864 B)
#define NSTG 3
#define GSMEM (NSTG*STAGE_PAIR)       // 110592 B

template<int EPI, int RND>
__global__ void __launch_bounds__(256, 2)
tc_gemm(const float* __restrict__ A, const float* __restrict__ Bt,
        const float* __restrict__ bias, const float* __restrict__ res,
        float* __restrict__ C, int M, int N, int K) {
    extern __shared__ float sm[];
    const int tid = threadIdx.x, lane = tid & 31, wid = tid >> 5;
    const int wm = wid & 1, wn = wid >> 1;          // warp grid 2(M) x 4(N)
    const int row0 = blockIdx.y * 128, col0 = blockIdx.x * 128;
    const int fr = lane >> 2, fk = lane & 3;

    const uint32_t sbase = smem_u32(sm);

    // loader mapping: 2 threads per row, 16 floats (4x cp.async 16B) each
    const int lrow = tid >> 1, lcg = (tid & 1) * 16;
    const float* Arow = A  + (size_t)(row0 + lrow) * K + lcg;
    const float* Brow = Bt + (size_t)(col0 + lrow) * K + lcg;
    const uint32_t sd = sbase + (uint32_t)(lrow*LDT + lcg) * 4;

    // ldmatrix per-thread addresses (byte offsets from stage base)
    const int r8 = lane & 7, g = lane >> 3;
    uint32_t a_off[4], b_off[2];
    #pragma unroll
    for (int mi = 0; mi < 4; mi++)
        a_off[mi] = sbase +
            (uint32_t)(((wm*64 + mi*16 + (g&1)*8 + r8)*LDT) + (g>>1)*4) * 4;
    #pragma unroll
    for (int n2 = 0; n2 < 2; n2++)
        b_off[n2] = sbase + STAGE_BYTES +
            (uint32_t)(((wn*32 + n2*16 + (g>>1)*8 + r8)*LDT) + (g&1)*4) * 4;

    float acc[4][4][4];
    #pragma unroll
    for (int i = 0; i < 4; i++)
        #pragma unroll
        for (int j = 0; j < 4; j++)
            #pragma unroll
            for (int c = 0; c < 4; c++) acc[i][j][c] = 0.f;

    const int NK = K >> 5;

    // prologue: stages 0 and 1
    #pragma unroll
    for (int p = 0; p < 2; p++) {
        uint32_t da = sd + p*STAGE_PAIR, db = da + STAGE_BYTES;
        const float* ga = Arow + p*32;
        const float* gb = Brow + p*32;
        #pragma unroll
        for (int u = 0; u < 4; u++) {
            CP_ASYNC16(da + u*16, ga + u*4);
            CP_ASYNC16(db + u*16, gb + u*4);
        }
        CP_COMMIT();
    }

    for (int kc = 0; kc < NK; kc++) {
        if (kc < NK - 1) { CP_WAIT(1); } else { CP_WAIT(0); }
        __syncthreads();               // stage kc ready; stage kc-1 fully consumed

        int s = kc % NSTG;
        uint32_t stb = (uint32_t)(s * STAGE_PAIR);
        #pragma unroll
        for (int ks = 0; ks < 4; ks++) {
            uint32_t af[4][4], bb[2][4];
            #pragma unroll
            for (int mi = 0; mi < 4; mi++)
                ldm_x4(af[mi], a_off[mi] + stb + ks*32);
            #pragma unroll
            for (int n2 = 0; n2 < 2; n2++)
                ldm_x4(bb[n2], b_off[n2] + stb + ks*32);
            #pragma unroll
            for (int mi = 0; mi < 4; mi++)
                #pragma unroll
                for (int ni = 0; ni < 4; ni++)
                    mma_tf32(acc[mi][ni], af[mi], &bb[ni>>1][(ni&1)*2]);
        }

        if (kc + 2 < NK) {             // load chunk kc+2 into stage (kc+2)%3
            int ns = (kc + 2) % NSTG;
            uint32_t da = sd + ns*STAGE_PAIR, db = da + STAGE_BYTES;
            const float* ga = Arow + (kc+2)*32;
            const float* gb = Brow + (kc+2)*32;
            #pragma unroll
            for (int u = 0; u < 4; u++) {
                CP_ASYNC16(da + u*16, ga + u*4);
                CP_ASYNC16(db + u*16, gb + u*4);
            }
            CP_COMMIT();
        }
    }

    // epilogue
    #pragma unroll
    for (int mi = 0; mi < 4; mi++) {
        int m = row0 + wm*64 + mi*16 + fr;
        #pragma unroll
        for (int ni = 0; ni < 4; ni++) {
            int n = col0 + wn*32 + ni*8 + 2*fk;
            float b0 = bias[n], b1 = bias[n+1];
            float v0 = acc[mi][ni][0] + b0;
            float v1 = acc[mi][ni][1] + b1;
            float v2 = acc[mi][ni][2] + b0;
            float v3 = acc[mi][ni][3] + b1;
            if (EPI == 1) {
                float2 r0 = *(const float2*)&res[(size_t)m*N + n];
                float2 r1 = *(const float2*)&res[(size_t)(m+8)*N + n];
                v0 += r0.x; v1 += r0.y; v2 += r1.x; v3 += r1.y;
            }
            if (EPI == 2) {
                v0 = gelu_exact(v0); v1 = gelu_exact(v1);
                v2 = gelu_exact(v2); v3 = gelu_exact(v3);
            }
            if (RND) {
                v0 = tf32f(v0); v1 = tf32f(v1); v2 = tf32f(v2); v3 = tf32f(v3);
            }
            *(float2*)&C[(size_t)m*N + n]     = make_float2(v0, v1);
            *(float2*)&C[(size_t)(m+8)*N + n] = make_float2(v2, v3);
        }
    }
}

// ===== tf32 mma flash attention: 128q x 64k tiles, D=64, ldmatrix ============
#define LQ 68                    // all smem strides (floats); rows 16B-aligned
#define ATTN_SMEM ((128*LQ + 64*LQ + 64*LQ + 128*LQ) * 4)   // Q,K,Vt,P

__global__ void __launch_bounds__(256)
attn_tc(const float* __restrict__ q, const float* __restrict__ k,
        const float* __restrict__ v, const int* __restrict__ mask,
        float* __restrict__ ctx) {
    extern __shared__ float sm[];
    float* Qs = sm;                  // [128][LQ]
    float* Ks = Qs + 128*LQ;         // [64][LQ]   ([key][d])
    float* Vt = Ks + 64*LQ;          // [64][LQ]   ([d][key])
    float* Ps = Vt + 64*LQ;          // [128][LQ]

    const int tid = threadIdx.x, lane = tid & 31, wid = tid >> 5;
    const int fr = lane >> 2, fk = lane & 3;
    const int h = blockIdx.y, b = blockIdx.z;
    const int q0 = blockIdx.x * 128;
    const int r0 = wid*16 + fr;
    const int r1 = r0 + 8;

    const uint32_t uQ = smem_u32(Qs), uK = smem_u32(Ks);
    const uint32_t uV = smem_u32(Vt), uP = smem_u32(Ps);

    // ldmatrix addresses
    const int r8 = lane & 7, g = lane >> 3;
    const uint32_t a_row = (uint32_t)((wid*16 + (g&1)*8 + r8)*LQ + (g>>1)*4) * 4;
    uint32_t qa_off = uQ + a_row;    // A fragments from Qs
    uint32_t pa_off = uP + a_row;    // A fragments from Ps
    uint32_t kb_off[4], vb_off[4];   // B fragments (4 x 16-n blocks = 64)
    #pragma unroll
    for (int j = 0; j < 4; j++) {
        uint32_t brow = (uint32_t)((j*16 + (g>>1)*8 + r8)*LQ + (g&1)*4) * 4;
        kb_off[j] = uK + brow;
        vb_off[j] = uV + brow;
    }

    // load Q tile (128 x 64)
    {
        int lrow = tid >> 1, half = (tid & 1) * 32;
        const float* qb = q + ((size_t)(b*Ss) + q0 + lrow)*Ee + h*Dd + half;
        float* dst = Qs + lrow*LQ + half;
        #pragma unroll
        for (int u = 0; u < 8; u++)
            *(float4*)(dst + u*4) = *(const float4*)(qb + u*4);
    }

    float acc_o[8][4];
    #pragma unroll
    for (int ni = 0; ni < 8; ni++)
        #pragma unroll
        for (int c = 0; c < 4; c++) acc_o[ni][c] = 0.f;
    float m0 = -1e30f, m1 = -1e30f, l0 = 0.f, l1 = 0.f;

    const int klr = tid >> 2, kc = (tid & 3) * 16;

    for (int kt = 0; kt < Ss/64; kt++) {
        int k0 = kt * 64;
        __syncthreads();
        {
            const float* kb = k + ((size_t)(b*Ss) + k0 + klr)*Ee + h*Dd + kc;
            const float* vb = v + ((size_t)(b*Ss) + k0 + klr)*Ee + h*Dd + kc;
            float* kd = Ks + klr*LQ + kc;
            #pragma unroll
            for (int u = 0; u < 4; u++) {
                *(float4*)(kd + u*4) = *(const float4*)(kb + u*4);
                float4 x2 = *(const float4*)(vb + u*4);
                Vt[(kc+u*4+0)*LQ + klr] = x2.x;
                Vt[(kc+u*4+1)*LQ + klr] = x2.y;
                Vt[(kc+u*4+2)*LQ + klr] = x2.z;
                Vt[(kc+u*4+3)*LQ + klr] = x2.w;
            }
        }
        __syncthreads();

        // S = Q K^T
        float accs[8][4];
        #pragma unroll
        for (int ni = 0; ni < 8; ni++)
            #pragma unroll
            for (int c = 0; c < 4; c++) accs[ni][c] = 0.f;

        #pragma unroll
        for (int ks = 0; ks < 8; ks++) {
            uint32_t af[4], bb[4][4];
            ldm_x4(af, qa_off + ks*32);
            #pragma unroll
            for (int j = 0; j < 4; j++)
                ldm_x4(bb[j], kb_off[j] + ks*32);
            #pragma unroll
            for (int ni = 0; ni < 8; ni++)
                mma_tf32(accs[ni], af, &bb[ni>>1][(ni&1)*2]);
        }

        // scale + mask + online softmax
        float rm0 = -1e30f, rm1 = -1e30f;
        #pragma unroll
        for (int ni = 0; ni < 8; ni++) {
            int col = b*Ss + k0 + ni*8 + 2*fk;
            int mk0 = mask[col], mk1 = mask[col+1];
            accs[ni][0] = mk0 ? accs[ni][0]*0.03125f : -1e9f;
            accs[ni][1] = mk1 ? accs[ni][1]*0.03125f : -1e9f;
            accs[ni][2] = mk0 ? accs[ni][2]*0.03125f : -1e9f;
            accs[ni][3] = mk1 ? accs[ni][3]*0.03125f : -1e9f;
            rm0 = fmaxf(rm0, fmaxf(accs[ni][0], accs[ni][1]));
            rm1 = fmaxf(rm1, fmaxf(accs[ni][2], accs[ni][3]));
        }
        rm0 = fmaxf(rm0, __shfl_xor_sync(0xffffffffu, rm0, 1));
        rm0 = fmaxf(rm0, __shfl_xor_sync(0xffffffffu, rm0, 2));
        rm1 = fmaxf(rm1, __shfl_xor_sync(0xffffffffu, rm1, 1));
        rm1 = fmaxf(rm1, __shfl_xor_sync(0xffffffffu, rm1, 2));

        float mn0 = fmaxf(m0, rm0), mn1 = fmaxf(m1, rm1);
        float a0 = __expf(m0 - mn0), a1 = __expf(m1 - mn1);
        m0 = mn0; m1 = mn1;

        float rs0 = 0.f, rs1 = 0.f;
        #pragma unroll
        for (int ni = 0; ni < 8; ni++) {
            accs[ni][0] = __expf(accs[ni][0] - mn0);
            accs[ni][1] = __expf(accs[ni][1] - mn0);
            accs[ni][2] = __expf(accs[ni][2] - mn1);
            accs[ni][3] = __expf(accs[ni][3] - mn1);
            rs0 += accs[ni][0] + accs[ni][1];
            rs1 += accs[ni][2] + accs[ni][3];
        }
        rs0 += __shfl_xor_sync(0xffffffffu, rs0, 1);
        rs0 += __shfl_xor_sync(0xffffffffu, rs0, 2);
        rs1 += __shfl_xor_sync(0xffffffffu, rs1, 1);
        rs1 += __shfl_xor_sync(0xffffffffu, rs1, 2);
        l0 = l0*a0 + rs0;
        l1 = l1*a1 + rs1;

        #pragma unroll
        for (int ni = 0; ni < 8; ni++) {
            acc_o[ni][0] *= a0; acc_o[ni][1] *= a0;
            acc_o[ni][2] *= a1; acc_o[ni][3] *= a1;
        }

        // P -> smem (tf32)
        #pragma unroll
        for (int ni = 0; ni < 8; ni++) {
            *(float2*)&Ps[r0*LQ + ni*8 + 2*fk] =
                make_float2(tf32f(accs[ni][0]), tf32f(accs[ni][1]));
            *(float2*)&Ps[r1*LQ + ni*8 + 2*fk] =
                make_float2(tf32f(accs[ni][2]), tf32f(accs[ni][3]));
        }
        __syncwarp();

        // O += P @ V
        #pragma unroll
        for (int ks = 0; ks < 8; ks++) {
            uint32_t af[4], bb[4][4];
            ldm_x4(af, pa_off + ks*32);
            #pragma unroll
            for (int j = 0; j < 4; j++)
                ldm_x4(bb[j], vb_off[j] + ks*32);
            #pragma unroll
            for (int ni = 0; ni < 8; ni++)
                mma_tf32(acc_o[ni], af, &bb[ni>>1][(ni&1)*2]);
        }
    }

    float i0 = 1.f / l0, i1 = 1.f / l1;
    size_t grow0 = (size_t)(b*Ss + q0 + r0) * Ee + h*Dd;
    size_t grow1 = (size_t)(b*Ss + q0 + r1) * Ee + h*Dd;
    #pragma unroll
    for (int ni = 0; ni < 8; ni++) {
        int col = ni*8 + 2*fk;
        *(float2*)&ctx[grow0 + col] =
            make_float2(tf32f(acc_o[ni][0]*i0), tf32f(acc_o[ni][1]*i0));
        *(float2*)&ctx[grow1 + col] =
            make_float2(tf32f(acc_o[ni][2]*i1), tf32f(acc_o[ni][3]*i1));
    }
}

// ---------------- launch ------------------------------------------------------
extern "C" void kernel_launch(void* const* d_in, const int* in_sizes, int n_in,
                              void* d_out, int out_size) {
    const float* I      = (const float*)d_in[0];
    const float* x      = (const float*)d_in[1];
    const int*   mask   = (const int*)  d_in[2];
    const float* wq     = (const float*)d_in[3];
    const float* bq     = (const float*)d_in[4];
    const float* wk     = (const float*)d_in[5];
    const float* bk     = (const float*)d_in[6];
    const float* wv     = (const float*)d_in[7];
    const float* bv     = (const float*)d_in[8];
    const float* w_proj = (const float*)d_in[9];
    const float* b_proj = (const float*)d_in[10];
    const float* g1     = (const float*)d_in[11];
    const float* be1    = (const float*)d_in[12];
    const float* g2     = (const float*)d_in[13];
    const float* be2    = (const float*)d_in[14];
    const float* w1     = (const float*)d_in[15];
    const float* b1     = (const float*)d_in[16];
    const float* w2     = (const float*)d_in[17];
    const float* b2     = (const float*)d_in[18];
    float* out = (float*)d_out;

    float *Ir, *xn, *qb, *kb, *vb, *ctx, *hb, *h2, *ffa;
    float *wqT, *wkT, *wvT, *wpT, *w1T, *w2T;
    cudaGetSymbolAddress((void**)&Ir,  g_Ir);
    cudaGetSymbolAddress((void**)&xn,  g_xn);
    cudaGetSymbolAddress((void**)&qb,  g_q);
    cudaGetSymbolAddress((void**)&kb,  g_k);
    cudaGetSymbolAddress((void**)&vb,  g_v);
    cudaGetSymbolAddress((void**)&ctx, g_ctx);
    cudaGetSymbolAddress((void**)&hb,  g_h);
    cudaGetSymbolAddress((void**)&h2,  g_h2);
    cudaGetSymbolAddress((void**)&ffa, g_ffa);
    cudaGetSymbolAddress((void**)&wqT, g_wqT);
    cudaGetSymbolAddress((void**)&wkT, g_wkT);
    cudaGetSymbolAddress((void**)&wvT, g_wvT);
    cudaGetSymbolAddress((void**)&wpT, g_wpT);
    cudaGetSymbolAddress((void**)&w1T, g_w1T);
    cudaGetSymbolAddress((void**)&w2T, g_w2T);

    cudaFuncSetAttribute(attn_tc, cudaFuncAttributeMaxDynamicSharedMemorySize, ATTN_SMEM);
    cudaFuncSetAttribute(tc_gemm<0,1>, cudaFuncAttributeMaxDynamicSharedMemorySize, GSMEM);
    cudaFuncSetAttribute(tc_gemm<1,0>, cudaFuncAttributeMaxDynamicSharedMemorySize, GSMEM);
    cudaFuncSetAttribute(tc_gemm<2,1>, cudaFuncAttributeMaxDynamicSharedMemorySize, GSMEM);

    // idx 0-2: per-head weight packs (needed by QKV GEMMs)
    int pe = (Ee*Ee + 255) / 256;
    pack_wT<<<pe, 256>>>(wq, wqT);
    pack_wT<<<pe, 256>>>(wk, wkT);
    pack_wT<<<pe, 256>>>(wv, wvT);
    // idx 3-4: activations
    round_k<<<MM*Ee/4/256, 256>>>(I, Ir);
    ln_k<<<MM, 256>>>(x, g1, be1, xn);

    // idx 5-7: QKV GEMMs (idx 5 = ncu capture target)
    dim3 gE(Ee/128, MM/128);
    tc_gemm<0,1><<<gE, 256, GSMEM>>>(Ir, wqT, bq, nullptr, qb, MM, Ee, Ee);
    tc_gemm<0,1><<<gE, 256, GSMEM>>>(xn, wkT, bk, nullptr, kb, MM, Ee, Ee);
    tc_gemm<0,1><<<gE, 256, GSMEM>>>(xn, wvT, bv, nullptr, vb, MM, Ee, Ee);

    // idx 8-10: dense weight transposes (needed from proj GEMM onward)
    transpose_k<<<dim3(Ee/32,   Ee/32),   dim3(32,8)>>>(w_proj, wpT, Ee,   Ee);
    transpose_k<<<dim3(4*Ee/32, Ee/32),   dim3(32,8)>>>(w1,     w1T, Ee,   4*Ee);
    transpose_k<<<dim3(Ee/32,   4*Ee/32), dim3(32,8)>>>(w2,     w2T, 4*Ee, Ee);

    attn_tc<<<dim3(Ss/128, Hh, Bb), 256, ATTN_SMEM>>>(qb, kb, vb, mask, ctx);

    tc_gemm<1,0><<<gE, 256, GSMEM>>>(ctx, wpT, b_proj, xn, hb, MM, Ee, Ee);

    ln_k<<<MM, 256>>>(hb, g2, be2, h2);

    dim3 gF1(4*Ee/128, MM/128);
    tc_gemm<2,1><<<gF1, 256, GSMEM>>>(h2, w1T, b1, nullptr, ffa, MM, 4*Ee, Ee);
    tc_gemm<1,0><<<gE, 256, GSMEM>>>(ffa, w2T, b2, h2, out, MM, Ee, 4*Ee);
}

// round 7
// speedup vs baseline: 3.2706x; 1.0854x over previous
#include <cuda_runtime.h>
#include <math.h>
#include <stdint.h>

#define Bb 2
#define Ss 2048
#define Ee 1024
#define Hh 16
#define Dd 64
#define MM (Bb*Ss)          // 4096 rows
#define EPSv 1e-5f

// ---------------- scratch (static device globals; no allocation) -------------
__device__ float g_Ir [MM*Ee];      // tf32-rounded I
__device__ float g_xn [MM*Ee];
__device__ float g_q  [MM*Ee];
__device__ float g_k  [MM*Ee];
__device__ float g_v  [MM*Ee];
__device__ float g_ctx[MM*Ee];
__device__ float g_h  [MM*Ee];
__device__ float g_h2 [MM*Ee];
__device__ float g_ffa[MM*4*Ee];
__device__ float g_wqT[Ee*Ee];      // [N,K] K-major, tf32-rounded
__device__ float g_wkT[Ee*Ee];
__device__ float g_wvT[Ee*Ee];
__device__ float g_wpT[Ee*Ee];
__device__ float g_w1T[4*Ee*Ee];    // [4E, E]
__device__ float g_w2T[Ee*4*Ee];    // [E, 4E]

// ---------------- helpers -----------------------------------------------------
__device__ __forceinline__ uint32_t smem_u32(const void* p) {
    uint32_t a;
    asm("{ .reg .u64 t; cvta.to.shared.u64 t, %1; cvt.u32.u64 %0, t; }"
        : "=r"(a) : "l"(p));
    return a;
}
__device__ __forceinline__ uint32_t f2tf32(float x) {
    uint32_t r;
    asm("cvt.rna.tf32.f32 %0, %1;" : "=r"(r) : "f"(x));
    return r;
}
__device__ __forceinline__ float tf32f(float x) { return __uint_as_float(f2tf32(x)); }
__device__ __forceinline__ void mma_tf32(float* d, const uint32_t* a, const uint32_t* b) {
    asm volatile(
        "mma.sync.aligned.m16n8k8.row.col.f32.tf32.tf32.f32 "
        "{%0,%1,%2,%3}, {%4,%5,%6,%7}, {%8,%9}, {%0,%1,%2,%3};"
        : "+f"(d[0]), "+f"(d[1]), "+f"(d[2]), "+f"(d[3])
        : "r"(a[0]), "r"(a[1]), "r"(a[2]), "r"(a[3]), "r"(b[0]), "r"(b[1]));
}
__device__ __forceinline__ void ldm_x4(uint32_t* r, uint32_t addr) {
    asm volatile("ldmatrix.sync.aligned.m8n8.x4.shared.b16 {%0,%1,%2,%3}, [%4];"
        : "=r"(r[0]), "=r"(r[1]), "=r"(r[2]), "=r"(r[3]) : "r"(addr));
}
#define CP_ASYNC16(dst, src) \
    asm volatile("cp.async.ca.shared.global [%0], [%1], 16;" :: "r"(dst), "l"(src))
#define CP_COMMIT() asm volatile("cp.async.commit_group;" ::: "memory")
#define CP_WAIT(n)  asm volatile("cp.async.wait_group %0;" :: "n"(n) : "memory")

// ---------------- one-shot tf32 rounding of I --------------------------------
__global__ void round_k(const float* __restrict__ in, float* __restrict__ out) {
    int i = blockIdx.x * blockDim.x + threadIdx.x;
    float4 v = ((const float4*)in)[i];
    float4 o;
    o.x = tf32f(v.x); o.y = tf32f(v.y); o.z = tf32f(v.z); o.w = tf32f(v.w);
    ((float4*)out)[i] = o;
}

// ---------------- weight repack: [H,E,D] -> [N=H*D, K=E], tf32-rounded --------
__global__ void pack_wT(const float* __restrict__ w, float* __restrict__ o) {
    int i = blockIdx.x * blockDim.x + threadIdx.x;   // i = n*E + e
    if (i < Ee*Ee) {
        int n = i / Ee, e = i % Ee;
        int h = n / Dd, d = n % Dd;
        o[i] = tf32f(w[(h*Ee + e)*Dd + d]);
    }
}

// ---------------- tiled transpose + tf32 round: in [R,C] -> out [C,R] ---------
__global__ void transpose_k(const float* __restrict__ in, float* __restrict__ out,
                            int R, int C) {
    __shared__ float t[32][33];
    int c = blockIdx.x*32 + threadIdx.x;
    int r0 = blockIdx.y*32;
    #pragma unroll
    for (int i = 0; i < 4; i++)
        t[threadIdx.y + i*8][threadIdx.x] = in[(size_t)(r0 + threadIdx.y + i*8)*C + c];
    __syncthreads();
    int c2 = r0 + threadIdx.x;
    int r2 = blockIdx.x*32;
    #pragma unroll
    for (int i = 0; i < 4; i++)
        out[(size_t)(r2 + threadIdx.y + i*8)*R + c2] = tf32f(t[threadIdx.x][threadIdx.y + i*8]);
}

// ---------------- LayerNorm (outputs tf32-rounded) ----------------------------
__global__ void ln_k(const float* __restrict__ x, const float* __restrict__ g,
                     const float* __restrict__ b, float* __restrict__ y) {
    int row = blockIdx.x;
    int t = threadIdx.x;
    float4 v = ((const float4*)(x + (size_t)row*Ee))[t];
    float s  = v.x + v.y + v.z + v.w;
    float sq = v.x*v.x + v.y*v.y + v.z*v.z + v.w*v.w;
    __shared__ float sh1[8], sh2[8];
    #pragma unroll
    for (int o = 16; o > 0; o >>= 1) {
        s  += __shfl_xor_sync(0xffffffffu, s,  o);
        sq += __shfl_xor_sync(0xffffffffu, sq, o);
    }
    int lane = t & 31, w = t >> 5;
    if (lane == 0) { sh1[w] = s; sh2[w] = sq; }
    __syncthreads();
    s = 0.f; sq = 0.f;
    #pragma unroll
    for (int i = 0; i < 8; i++) { s += sh1[i]; sq += sh2[i]; }
    float mu  = s  * (1.f/Ee);
    float var = sq * (1.f/Ee) - mu*mu;
    float rs  = rsqrtf(var + EPSv);
    float4 gv = ((const float4*)g)[t];
    float4 bv = ((const float4*)b)[t];
    float4 o4;
    o4.x = tf32f((v.x - mu)*rs*gv.x + bv.x);
    o4.y = tf32f((v.y - mu)*rs*gv.y + bv.y);
    o4.z = tf32f((v.z - mu)*rs*gv.z + bv.z);
    o4.w = tf32f((v.w - mu)*rs*gv.w + bv.w);
    ((float4*)(y + (size_t)row*Ee))[t] = o4;
}

// == tf32 GEMM: 128x256 CTA tile, warp 64x64, Kc=32, 3-stage cp.async =========
__device__ __forceinline__ float gelu_exact(float x) {
    return 0.5f * x * (1.0f + erff(x * 0.7071067811865476f));
}

#define LDT 36                         // smem row stride (floats)
#define A_BYTES (128*LDT*4)            // 18432
#define B_BYTES (256*LDT*4)            // 36864
#define STAGE_PAIR (A_BYTES + B_BYTES) // 55296
#define NSTG 3
#define GSMEM (NSTG*STAGE_PAIR)        // 165888

template<int EPI, int RND>
__global__ void __launch_bounds__(256, 1)
tc_gemm(const float* __restrict__ A, const float* __restrict__ Bt,
        const float* __restrict__ bias, const float* __restrict__ res,
        float* __restrict__ C, int M, int N, int K) {
    extern __shared__ float sm[];
    const int tid = threadIdx.x, lane = tid & 31, wid = tid >> 5;
    const int wm = wid & 1, wn = wid >> 1;          // warp grid 2(M) x 4(N)
    const int row0 = blockIdx.y * 128, col0 = blockIdx.x * 256;
    const int fr = lane >> 2, fk = lane & 3;

    const uint32_t sbase = smem_u32(sm);

    // A loader: 2 threads/row, 16 floats each. B loader: 1 thread/row, 32 floats.
    const int alrow = tid >> 1, alcg = (tid & 1) * 16;
    const float* Arow = A  + (size_t)(row0 + alrow) * K + alcg;
    const float* Brow = Bt + (size_t)(col0 + tid) * K;
    const uint32_t sda = sbase + (uint32_t)(alrow*LDT + alcg) * 4;
    const uint32_t sdb = sbase + A_BYTES + (uint32_t)(tid*LDT) * 4;

    // ldmatrix per-thread addresses (byte offsets from stage base)
    const int r8 = lane & 7, g = lane >> 3;
    uint32_t a_off[4], b_off[4];
    #pragma unroll
    for (int mi = 0; mi < 4; mi++)
        a_off[mi] = sbase +
            (uint32_t)(((wm*64 + mi*16 + (g&1)*8 + r8)*LDT) + (g>>1)*4) * 4;
    #pragma unroll
    for (int j = 0; j < 4; j++)
        b_off[j] = sbase + A_BYTES +
            (uint32_t)(((wn*64 + j*16 + (g>>1)*8 + r8)*LDT) + (g&1)*4) * 4;

    float acc[4][8][4];
    #pragma unroll
    for (int i = 0; i < 4; i++)
        #pragma unroll
        for (int j = 0; j < 8; j++)
            #pragma unroll
            for (int c = 0; c < 4; c++) acc[i][j][c] = 0.f;

    const int NK = K >> 5;

    // prologue: stages 0 and 1
    #pragma unroll
    for (int p = 0; p < 2; p++) {
        uint32_t da = sda + p*STAGE_PAIR, db = sdb + p*STAGE_PAIR;
        const float* ga = Arow + p*32;
        const float* gb = Brow + p*32;
        #pragma unroll
        for (int u = 0; u < 4; u++) CP_ASYNC16(da + u*16, ga + u*4);
        #pragma unroll
        for (int u = 0; u < 8; u++) CP_ASYNC16(db + u*16, gb + u*4);
        CP_COMMIT();
    }

    for (int kc = 0; kc < NK; kc++) {
        if (kc < NK - 1) { CP_WAIT(1); } else { CP_WAIT(0); }
        __syncthreads();               // stage kc ready; stage kc-1 fully consumed

        uint32_t stb = (uint32_t)((kc % NSTG) * STAGE_PAIR);
        #pragma unroll
        for (int ks = 0; ks < 4; ks++) {
            uint32_t af[4][4], bb[4][4];
            #pragma unroll
            for (int mi = 0; mi < 4; mi++)
                ldm_x4(af[mi], a_off[mi] + stb + ks*32);
            #pragma unroll
            for (int j = 0; j < 4; j++)
                ldm_x4(bb[j], b_off[j] + stb + ks*32);
            #pragma unroll
            for (int mi = 0; mi < 4; mi++)
                #pragma unroll
                for (int ni = 0; ni < 8; ni++)
                    mma_tf32(acc[mi][ni], af[mi], &bb[ni>>1][(ni&1)*2]);
        }

        if (kc + 2 < NK) {             // load chunk kc+2 into stage (kc+2)%3
            uint32_t stn = (uint32_t)(((kc + 2) % NSTG) * STAGE_PAIR);
            uint32_t da = sda + stn, db = sdb + stn;
            const float* ga = Arow + (kc+2)*32;
            const float* gb = Brow + (kc+2)*32;
            #pragma unroll
            for (int u = 0; u < 4; u++) CP_ASYNC16(da + u*16, ga + u*4);
            #pragma unroll
            for (int u = 0; u < 8; u++) CP_ASYNC16(db + u*16, gb + u*4);
            CP_COMMIT();
        }
    }

    // epilogue
    #pragma unroll
    for (int mi = 0; mi < 4; mi++) {
        int m = row0 + wm*64 + mi*16 + fr;
        #pragma unroll
        for (int ni = 0; ni < 8; ni++) {
            int n = col0 + wn*64 + ni*8 + 2*fk;
            float b0 = bias[n], b1 = bias[n+1];
            float v0 = acc[mi][ni][0] + b0;
            float v1 = acc[mi][ni][1] + b1;
            float v2 = acc[mi][ni][2] + b0;
            float v3 = acc[mi][ni][3] + b1;
            if (EPI == 1) {
                float2 r0 = *(const float2*)&res[(size_t)m*N + n];
                float2 r1 = *(const float2*)&res[(size_t)(m+8)*N + n];
                v0 += r0.x; v1 += r0.y; v2 += r1.x; v3 += r1.y;
            }
            if (EPI == 2) {
                v0 = gelu_exact(v0); v1 = gelu_exact(v1);
                v2 = gelu_exact(v2); v3 = gelu_exact(v3);
            }
            if (RND) {
                v0 = tf32f(v0); v1 = tf32f(v1); v2 = tf32f(v2); v3 = tf32f(v3);
            }
            *(float2*)&C[(size_t)m*N + n]     = make_float2(v0, v1);
            *(float2*)&C[(size_t)(m+8)*N + n] = make_float2(v2, v3);
        }
    }
}

// ===== tf32 mma flash attention: 128q x 64k tiles, D=64, ldmatrix ============
#define LQ 68                    // all smem strides (floats); rows 16B-aligned
#define ATTN_SMEM ((128*LQ + 64*LQ + 64*LQ + 128*LQ) * 4)   // Q,K,Vt,P

__global__ void __launch_bounds__(256)
attn_tc(const float* __restrict__ q, const float* __restrict__ k,
        const float* __restrict__ v, const int* __restrict__ mask,
        float* __restrict__ ctx) {
    extern __shared__ float sm[];
    float* Qs = sm;                  // [128][LQ]
    float* Ks = Qs + 128*LQ;         // [64][LQ]   ([key][d])
    float* Vt = Ks + 64*LQ;          // [64][LQ]   ([d][key])
    float* Ps = Vt + 64*LQ;          // [128][LQ]

    const int tid = threadIdx.x, lane = tid & 31, wid = tid >> 5;
    const int fr = lane >> 2, fk = lane & 3;
    const int h = blockIdx.y, b = blockIdx.z;
    const int q0 = blockIdx.x * 128;
    const int r0 = wid*16 + fr;
    const int r1 = r0 + 8;

    const uint32_t uQ = smem_u32(Qs), uK = smem_u32(Ks);
    const uint32_t uV = smem_u32(Vt), uP = smem_u32(Ps);

    // ldmatrix addresses
    const int r8 = lane & 7, g = lane >> 3;
    const uint32_t a_row = (uint32_t)((wid*16 + (g&1)*8 + r8)*LQ + (g>>1)*4) * 4;
    uint32_t qa_off = uQ + a_row;    // A fragments from Qs
    uint32_t pa_off = uP + a_row;    // A fragments from Ps
    uint32_t kb_off[4], vb_off[4];   // B fragments (4 x 16-n blocks = 64)
    #pragma unroll
    for (int j = 0; j < 4; j++) {
        uint32_t brow = (uint32_t)((j*16 + (g>>1)*8 + r8)*LQ + (g&1)*4) * 4;
        kb_off[j] = uK + brow;
        vb_off[j] = uV + brow;
    }

    // load Q tile (128 x 64)
    {
        int lrow = tid >> 1, half = (tid & 1) * 32;
        const float* qb = q + ((size_t)(b*Ss) + q0 + lrow)*Ee + h*Dd + half;
        float* dst = Qs + lrow*LQ + half;
        #pragma unroll
        for (int u = 0; u < 8; u++)
            *(float4*)(dst + u*4) = *(const float4*)(qb + u*4);
    }

    float acc_o[8][4];
    #pragma unroll
    for (int ni = 0; ni < 8; ni++)
        #pragma unroll
        for (int c = 0; c < 4; c++) acc_o[ni][c] = 0.f;
    float m0 = -1e30f, m1 = -1e30f, l0 = 0.f, l1 = 0.f;

    const int klr = tid >> 2, kc = (tid & 3) * 16;

    for (int kt = 0; kt < Ss/64; kt++) {
        int k0 = kt * 64;
        __syncthreads();
        {
            const float* kb = k + ((size_t)(b*Ss) + k0 + klr)*Ee + h*Dd + kc;
            const float* vb = v + ((size_t)(b*Ss) + k0 + klr)*Ee + h*Dd + kc;
            float* kd = Ks + klr*LQ + kc;
            #pragma unroll
            for (int u = 0; u < 4; u++) {
                *(float4*)(kd + u*4) = *(const float4*)(kb + u*4);
                float4 x2 = *(const float4*)(vb + u*4);
                Vt[(kc+u*4+0)*LQ + klr] = x2.x;
                Vt[(kc+u*4+1)*LQ + klr] = x2.y;
                Vt[(kc+u*4+2)*LQ + klr] = x2.z;
                Vt[(kc+u*4+3)*LQ + klr] = x2.w;
            }
        }
        __syncthreads();

        // S = Q K^T
        float accs[8][4];
        #pragma unroll
        for (int ni = 0; ni < 8; ni++)
            #pragma unroll
            for (int c = 0; c < 4; c++) accs[ni][c] = 0.f;

        #pragma unroll
        for (int ks = 0; ks < 8; ks++) {
            uint32_t af[4], bb[4][4];
            ldm_x4(af, qa_off + ks*32);
            #pragma unroll
            for (int j = 0; j < 4; j++)
                ldm_x4(bb[j], kb_off[j] + ks*32);
            #pragma unroll
            for (int ni = 0; ni < 8; ni++)
                mma_tf32(accs[ni], af, &bb[ni>>1][(ni&1)*2]);
        }

        // scale + mask + online softmax
        float rm0 = -1e30f, rm1 = -1e30f;
        #pragma unroll
        for (int ni = 0; ni < 8; ni++) {
            int col = b*Ss + k0 + ni*8 + 2*fk;
            int mk0 = mask[col], mk1 = mask[col+1];
            accs[ni][0] = mk0 ? accs[ni][0]*0.03125f : -1e9f;
            accs[ni][1] = mk1 ? accs[ni][1]*0.03125f : -1e9f;
            accs[ni][2] = mk0 ? accs[ni][2]*0.03125f : -1e9f;
            accs[ni][3] = mk1 ? accs[ni][3]*0.03125f : -1e9f;
            rm0 = fmaxf(rm0, fmaxf(accs[ni][0], accs[ni][1]));
            rm1 = fmaxf(rm1, fmaxf(accs[ni][2], accs[ni][3]));
        }
        rm0 = fmaxf(rm0, __shfl_xor_sync(0xffffffffu, rm0, 1));
        rm0 = fmaxf(rm0, __shfl_xor_sync(0xffffffffu, rm0, 2));
        rm1 = fmaxf(rm1, __shfl_xor_sync(0xffffffffu, rm1, 1));
        rm1 = fmaxf(rm1, __shfl_xor_sync(0xffffffffu, rm1, 2));

        float mn0 = fmaxf(m0, rm0), mn1 = fmaxf(m1, rm1);
        float a0 = __expf(m0 - mn0), a1 = __expf(m1 - mn1);
        m0 = mn0; m1 = mn1;

        float rs0 = 0.f, rs1 = 0.f;
        #pragma unroll
        for (int ni = 0; ni < 8; ni++) {
            accs[ni][0] = __expf(accs[ni][0] - mn0);
            accs[ni][1] = __expf(accs[ni][1] - mn0);
            accs[ni][2] = __expf(accs[ni][2] - mn1);
            accs[ni][3] = __expf(accs[ni][3] - mn1);
            rs0 += accs[ni][0] + accs[ni][1];
            rs1 += accs[ni][2] + accs[ni][3];
        }
        rs0 += __shfl_xor_sync(0xffffffffu, rs0, 1);
        rs0 += __shfl_xor_sync(0xffffffffu, rs0, 2);
        rs1 += __shfl_xor_sync(0xffffffffu, rs1, 1);
        rs1 += __shfl_xor_sync(0xffffffffu, rs1, 2);
        l0 = l0*a0 + rs0;
        l1 = l1*a1 + rs1;

        #pragma unroll
        for (int ni = 0; ni < 8; ni++) {
            acc_o[ni][0] *= a0; acc_o[ni][1] *= a0;
            acc_o[ni][2] *= a1; acc_o[ni][3] *= a1;
        }

        // P -> smem (tf32)
        #pragma unroll
        for (int ni = 0; ni < 8; ni++) {
            *(float2*)&Ps[r0*LQ + ni*8 + 2*fk] =
                make_float2(tf32f(accs[ni][0]), tf32f(accs[ni][1]));
            *(float2*)&Ps[r1*LQ + ni*8 + 2*fk] =
                make_float2(tf32f(accs[ni][2]), tf32f(accs[ni][3]));
        }
        __syncwarp();

        // O += P @ V
        #pragma unroll
        for (int ks = 0; ks < 8; ks++) {
            uint32_t af[4], bb[4][4];
            ldm_x4(af, pa_off + ks*32);
            #pragma unroll
            for (int j = 0; j < 4; j++)
                ldm_x4(bb[j], vb_off[j] + ks*32);
            #pragma unroll
            for (int ni = 0; ni < 8; ni++)
                mma_tf32(acc_o[ni], af, &bb[ni>>1][(ni&1)*2]);
        }
    }

    float i0 = 1.f / l0, i1 = 1.f / l1;
    size_t grow0 = (size_t)(b*Ss + q0 + r0) * Ee + h*Dd;
    size_t grow1 = (size_t)(b*Ss + q0 + r1) * Ee + h*Dd;
    #pragma unroll
    for (int ni = 0; ni < 8; ni++) {
        int col = ni*8 + 2*fk;
        *(float2*)&ctx[grow0 + col] =
            make_float2(tf32f(acc_o[ni][0]*i0), tf32f(acc_o[ni][1]*i0));
        *(float2*)&ctx[grow1 + col] =
            make_float2(tf32f(acc_o[ni][2]*i1), tf32f(acc_o[ni][3]*i1));
    }
}

// ---------------- launch ------------------------------------------------------
extern "C" void kernel_launch(void* const* d_in, const int* in_sizes, int n_in,
                              void* d_out, int out_size) {
    const float* I      = (const float*)d_in[0];
    const float* x      = (const float*)d_in[1];
    const int*   mask   = (const int*)  d_in[2];
    const float* wq     = (const float*)d_in[3];
    const float* bq     = (const float*)d_in[4];
    const float* wk     = (const float*)d_in[5];
    const float* bk     = (const float*)d_in[6];
    const float* wv     = (const float*)d_in[7];
    const float* bv     = (const float*)d_in[8];
    const float* w_proj = (const float*)d_in[9];
    const float* b_proj = (const float*)d_in[10];
    const float* g1     = (const float*)d_in[11];
    const float* be1    = (const float*)d_in[12];
    const float* g2     = (const float*)d_in[13];
    const float* be2    = (const float*)d_in[14];
    const float* w1     = (const float*)d_in[15];
    const float* b1     = (const float*)d_in[16];
    const float* w2     = (const float*)d_in[17];
    const float* b2     = (const float*)d_in[18];
    float* out = (float*)d_out;

    float *Ir, *xn, *qb, *kb, *vb, *ctx, *hb, *h2, *ffa;
    float *wqT, *wkT, *wvT, *wpT, *w1T, *w2T;
    cudaGetSymbolAddress((void**)&Ir,  g_Ir);
    cudaGetSymbolAddress((void**)&xn,  g_xn);
    cudaGetSymbolAddress((void**)&qb,  g_q);
    cudaGetSymbolAddress((void**)&kb,  g_k);
    cudaGetSymbolAddress((void**)&vb,  g_v);
    cudaGetSymbolAddress((void**)&ctx, g_ctx);
    cudaGetSymbolAddress((void**)&hb,  g_h);
    cudaGetSymbolAddress((void**)&h2,  g_h2);
    cudaGetSymbolAddress((void**)&ffa, g_ffa);
    cudaGetSymbolAddress((void**)&wqT, g_wqT);
    cudaGetSymbolAddress((void**)&wkT, g_wkT);
    cudaGetSymbolAddress((void**)&wvT, g_wvT);
    cudaGetSymbolAddress((void**)&wpT, g_wpT);
    cudaGetSymbolAddress((void**)&w1T, g_w1T);
    cudaGetSymbolAddress((void**)&w2T, g_w2T);

    cudaFuncSetAttribute(attn_tc, cudaFuncAttributeMaxDynamicSharedMemorySize, ATTN_SMEM);
    cudaFuncSetAttribute(tc_gemm<0,1>, cudaFuncAttributeMaxDynamicSharedMemorySize, GSMEM);
    cudaFuncSetAttribute(tc_gemm<1,0>, cudaFuncAttributeMaxDynamicSharedMemorySize, GSMEM);
    cudaFuncSetAttribute(tc_gemm<2,1>, cudaFuncAttributeMaxDynamicSharedMemorySize, GSMEM);

    // weight packs / activation prep
    int pe = (Ee*Ee + 255) / 256;
    pack_wT<<<pe, 256>>>(wq, wqT);
    pack_wT<<<pe, 256>>>(wk, wkT);
    pack_wT<<<pe, 256>>>(wv, wvT);
    round_k<<<MM*Ee/4/256, 256>>>(I, Ir);
    ln_k<<<MM, 256>>>(x, g1, be1, xn);

    // QKV GEMMs
    dim3 gE(Ee/256, MM/128);
    tc_gemm<0,1><<<gE, 256, GSMEM>>>(Ir, wqT, bq, nullptr, qb, MM, Ee, Ee);
    tc_gemm<0,1><<<gE, 256, GSMEM>>>(xn, wkT, bk, nullptr, kb, MM, Ee, Ee);
    tc_gemm<0,1><<<gE, 256, GSMEM>>>(xn, wvT, bv, nullptr, vb, MM, Ee, Ee);

    // dense weight transposes (needed from proj GEMM onward)
    transpose_k<<<dim3(Ee/32,   Ee/32),   dim3(32,8)>>>(w_proj, wpT, Ee,   Ee);
    transpose_k<<<dim3(4*Ee/32, Ee/32),   dim3(32,8)>>>(w1,     w1T, Ee,   4*Ee);
    transpose_k<<<dim3(Ee/32,   4*Ee/32), dim3(32,8)>>>(w2,     w2T, 4*Ee, Ee);

    attn_tc<<<dim3(Ss/128, Hh, Bb), 256, ATTN_SMEM>>>(qb, kb, vb, mask, ctx);

    tc_gemm<1,0><<<gE, 256, GSMEM>>>(ctx, wpT, b_proj, xn, hb, MM, Ee, Ee);

    ln_k<<<MM, 256>>>(hb, g2, be2, h2);

    dim3 gF1(4*Ee/256, MM/128);
    tc_gemm<2,1><<<gF1, 256, GSMEM>>>(h2, w1T, b1, nullptr, ffa, MM, 4*Ee, Ee);
    tc_gemm<1,0><<<gE, 256, GSMEM>>>(ffa, w2T, b2, h2, out, MM, Ee, 4*Ee);
}